// round 2
// baseline (speedup 1.0000x reference)
#include <cuda_runtime.h>
#include <cuda_bf16.h>
#include <cstdint>

// Problem constants
#define BATCH 4
#define SEQ   2048
#define KDIM  1024
#define HEADS 16
#define HDIM  64
#define MROWS (BATCH * SEQ)          // 8192
#define QK_SCALE 0.35355339059327373f // 64^(-1/4)

// Scratch (device globals — no allocations allowed)
__device__ float g_q[BATCH * HEADS * SEQ * HDIM];  // [b][h][t][d]
__device__ float g_k[BATCH * HEADS * SEQ * HDIM];
__device__ float g_v[BATCH * HEADS * SEQ * HDIM];
__device__ float g_o[BATCH * SEQ * KDIM];          // [b][t][h*64+d]

// ---------------------------------------------------------------------------
// GEMM: C[m,n] = sum_k A[m,k] * W[n,k]   (A row-major [M,1024], W row-major [1024,1024])
// Tile 128x128, BK=16, 256 threads, 8x8 micro-tiles (split 4+4 layout).
// MODE 0: QKV projection — z selects W/out, writes [b][h][t][d] with scale.
// MODE 1: output projection — reads g_o, adds bias, writes plain row-major.
// ---------------------------------------------------------------------------
template <int MODE>
__global__ void __launch_bounds__(256)
gemm_kernel(const float* __restrict__ A,
            const float* __restrict__ W0,
            const float* __restrict__ W1,
            const float* __restrict__ W2,
            const float* __restrict__ bias,
            float* __restrict__ outPlain)
{
    const int tid = threadIdx.x;
    const int tx = tid & 15;      // 0..15 (n groups)
    const int ty = tid >> 4;      // 0..15 (m groups)

    const float* W = W0;
    float* outQKV = nullptr;
    float scale = 1.0f;
    if (MODE == 0) {
        const int z = blockIdx.z;
        W      = (z == 0) ? W0 : (z == 1) ? W1 : W2;
        outQKV = (z == 0) ? g_q : (z == 1) ? g_k : g_v;
        scale  = (z == 2) ? 1.0f : QK_SCALE;
    }

    __shared__ __align__(16) float As[16][132];
    __shared__ __align__(16) float Bs[16][132];

    const int mBase = blockIdx.y * 128;
    const int nBase = blockIdx.x * 128;

    // Global load mapping: 128 rows x 16 cols per tile; thread loads 2 float4.
    const int ldRow = tid >> 2;        // 0..63
    const int ldC   = (tid & 3) * 4;   // 0,4,8,12

    const float* Aptr = A + (size_t)(mBase + ldRow) * KDIM + ldC;
    const float* Bptr = W + (size_t)(nBase + ldRow) * KDIM + ldC;

    float4 ra0 = *(const float4*)(Aptr);
    float4 ra1 = *(const float4*)(Aptr + (size_t)64 * KDIM);
    float4 rb0 = *(const float4*)(Bptr);
    float4 rb1 = *(const float4*)(Bptr + (size_t)64 * KDIM);

    float acc[8][8];
#pragma unroll
    for (int i = 0; i < 8; i++)
#pragma unroll
        for (int j = 0; j < 8; j++) acc[i][j] = 0.0f;

#pragma unroll 1
    for (int kt = 0; kt < KDIM / 16; ++kt) {
        // stage registers -> smem (transposed)
        As[ldC + 0][ldRow] = ra0.x;  As[ldC + 1][ldRow] = ra0.y;
        As[ldC + 2][ldRow] = ra0.z;  As[ldC + 3][ldRow] = ra0.w;
        As[ldC + 0][ldRow + 64] = ra1.x;  As[ldC + 1][ldRow + 64] = ra1.y;
        As[ldC + 2][ldRow + 64] = ra1.z;  As[ldC + 3][ldRow + 64] = ra1.w;
        Bs[ldC + 0][ldRow] = rb0.x;  Bs[ldC + 1][ldRow] = rb0.y;
        Bs[ldC + 2][ldRow] = rb0.z;  Bs[ldC + 3][ldRow] = rb0.w;
        Bs[ldC + 0][ldRow + 64] = rb1.x;  Bs[ldC + 1][ldRow + 64] = rb1.y;
        Bs[ldC + 2][ldRow + 64] = rb1.z;  Bs[ldC + 3][ldRow + 64] = rb1.w;
        __syncthreads();

        if (kt < KDIM / 16 - 1) {   // prefetch next tile into registers
            Aptr += 16; Bptr += 16;
            ra0 = *(const float4*)(Aptr);
            ra1 = *(const float4*)(Aptr + (size_t)64 * KDIM);
            rb0 = *(const float4*)(Bptr);
            rb1 = *(const float4*)(Bptr + (size_t)64 * KDIM);
        }

#pragma unroll
        for (int k = 0; k < 16; ++k) {
            float a[8], b[8];
            float4 a0 = *(const float4*)&As[k][ty * 4];
            float4 a1 = *(const float4*)&As[k][64 + ty * 4];
            float4 b0 = *(const float4*)&Bs[k][tx * 4];
            float4 b1 = *(const float4*)&Bs[k][64 + tx * 4];
            a[0]=a0.x; a[1]=a0.y; a[2]=a0.z; a[3]=a0.w;
            a[4]=a1.x; a[5]=a1.y; a[6]=a1.z; a[7]=a1.w;
            b[0]=b0.x; b[1]=b0.y; b[2]=b0.z; b[3]=b0.w;
            b[4]=b1.x; b[5]=b1.y; b[6]=b1.z; b[7]=b1.w;
#pragma unroll
            for (int i = 0; i < 8; i++)
#pragma unroll
                for (int j = 0; j < 8; j++) acc[i][j] += a[i] * b[j];
        }
        __syncthreads();
    }

    // Epilogue
#pragma unroll
    for (int i = 0; i < 8; i++) {
        const int r = mBase + ((i < 4) ? (ty * 4 + i) : (64 + ty * 4 + i - 4));
        const int b_ = r >> 11;          // / SEQ
        const int t_ = r & (SEQ - 1);
#pragma unroll
        for (int j = 0; j < 8; j++) {
            const int n = nBase + ((j < 4) ? (tx * 4 + j) : (64 + tx * 4 + j - 4));
            const float v = acc[i][j];
            if (MODE == 0) {
                outQKV[(((size_t)(b_ * HEADS + (n >> 6)) * SEQ + t_) << 6) + (n & 63)] = v * scale;
            } else {
                outPlain[(size_t)r * KDIM + n] = v + bias[n];
            }
        }
    }
}

// ---------------------------------------------------------------------------
// Robust length decoding: the reference declares int64 but JAX (x64 disabled)
// typically materializes int32. lengths[b] ∈ [1, 2048] so values are always
// >= 1. If the buffer is int64 (little-endian), the high words at i32 indices
// 1 and 3 are 0; if int32, those slots hold lengths[1], lengths[3] >= 1.
// ---------------------------------------------------------------------------
__device__ __forceinline__ int decode_length(const int* l32, int b)
{
    const bool is64 = (l32[1] == 0) && (l32[3] == 0);
    return is64 ? l32[2 * b] : l32[b];
}

// ---------------------------------------------------------------------------
// Flash attention (fp32, online softmax).
// Block: one (b, h, 64-query tile). 256 threads = 16x16.
// K-tiles of 32 keys. S tile 64x32 (4q x 2k per thread), O tile 64x64
// (4q x 4d per thread). P routed through smem for the PV pass.
// ---------------------------------------------------------------------------
__global__ void __launch_bounds__(256)
attn_kernel(const int* __restrict__ lengths32)
{
    const int b  = blockIdx.z;
    const int h  = blockIdx.y;
    const int q0 = blockIdx.x * 64;
    const int tid = threadIdx.x;
    const int tx = tid & 15;
    const int ty = tid >> 4;

    __shared__ __align__(16) float Qs[64][68]; // [d][q]
    __shared__ __align__(16) float Ks[64][36]; // [d][k]
    __shared__ __align__(16) float Vs[32][68]; // [k][d]
    __shared__ __align__(16) float Ps[64][36]; // [q][k]

    const size_t headBase = (size_t)(b * HEADS + h) * SEQ * HDIM;
    const float* Qg = g_q + headBase + (size_t)q0 * HDIM;
    const float* Kg = g_k + headBase;
    const float* Vg = g_v + headBase;

    // Load Q tile transposed: 1024 float4, 4/thread, row-minor mapping
#pragma unroll
    for (int i = 0; i < 4; i++) {
        const int f = tid + i * 256;
        const int row = f & 63;
        const int c4 = f >> 6;           // 0..15
        float4 v = *(const float4*)(Qg + row * HDIM + c4 * 4);
        Qs[c4 * 4 + 0][row] = v.x;
        Qs[c4 * 4 + 1][row] = v.y;
        Qs[c4 * 4 + 2][row] = v.z;
        Qs[c4 * 4 + 3][row] = v.w;
    }

    const int len = decode_length(lengths32, b);

    float m_r[4], l_r[4], acc[4][4];
#pragma unroll
    for (int qi = 0; qi < 4; qi++) {
        m_r[qi] = -1e30f;
        l_r[qi] = 0.0f;
#pragma unroll
        for (int dj = 0; dj < 4; dj++) acc[qi][dj] = 0.0f;
    }

    __syncthreads();

    for (int kt = 0; kt < SEQ / 32; ++kt) {
        const int kb = kt * 32;
        // Load K (transposed, row-minor for conflict-free stores) and V (natural)
#pragma unroll
        for (int i = 0; i < 2; i++) {
            const int f = tid + i * 256;
            {
                const int row = f & 31;
                const int c4 = f >> 5;   // 0..15
                float4 v = *(const float4*)(Kg + (size_t)(kb + row) * HDIM + c4 * 4);
                Ks[c4 * 4 + 0][row] = v.x;
                Ks[c4 * 4 + 1][row] = v.y;
                Ks[c4 * 4 + 2][row] = v.z;
                Ks[c4 * 4 + 3][row] = v.w;
            }
            {
                const int rowv = f >> 4;     // 0..31
                const int c4v = f & 15;
                float4 w = *(const float4*)(Vg + (size_t)(kb + rowv) * HDIM + c4v * 4);
                *(float4*)&Vs[rowv][c4v * 4] = w;
            }
        }
        __syncthreads();

        // S = Q K^T (64x32), 4q x 2k per thread
        float s[4][2];
#pragma unroll
        for (int qi = 0; qi < 4; qi++) { s[qi][0] = 0.0f; s[qi][1] = 0.0f; }
#pragma unroll 8
        for (int d = 0; d < 64; ++d) {
            float4 a = *(const float4*)&Qs[d][ty * 4];
            float2 kk = *(const float2*)&Ks[d][tx * 2];
            s[0][0] += a.x * kk.x;  s[0][1] += a.x * kk.y;
            s[1][0] += a.y * kk.x;  s[1][1] += a.y * kk.y;
            s[2][0] += a.z * kk.x;  s[2][1] += a.z * kk.y;
            s[3][0] += a.w * kk.x;  s[3][1] += a.w * kk.y;
        }

        // additive key-padding penalty
#pragma unroll
        for (int kj = 0; kj < 2; kj++) {
            const int kidx = kb + tx * 2 + kj;
            if (kidx >= len) {
#pragma unroll
                for (int qi = 0; qi < 4; qi++) s[qi][kj] += -10000.0f;
            }
        }

        // online softmax update (row reductions across the 16 tx lanes)
#pragma unroll
        for (int qi = 0; qi < 4; qi++) {
            float tm = fmaxf(s[qi][0], s[qi][1]);
#pragma unroll
            for (int msk = 1; msk < 16; msk <<= 1)
                tm = fmaxf(tm, __shfl_xor_sync(0xffffffffu, tm, msk));
            const float mn = fmaxf(m_r[qi], tm);
            const float alpha = __expf(m_r[qi] - mn);
            const float p0 = __expf(s[qi][0] - mn);
            const float p1 = __expf(s[qi][1] - mn);
            float ts = p0 + p1;
#pragma unroll
            for (int msk = 1; msk < 16; msk <<= 1)
                ts += __shfl_xor_sync(0xffffffffu, ts, msk);
            l_r[qi] = l_r[qi] * alpha + ts;
            m_r[qi] = mn;
#pragma unroll
            for (int dj = 0; dj < 4; dj++) acc[qi][dj] *= alpha;
            s[qi][0] = p0;
            s[qi][1] = p1;
        }

        // write P tile
#pragma unroll
        for (int qi = 0; qi < 4; qi++)
            *(float2*)&Ps[ty * 4 + qi][tx * 2] = make_float2(s[qi][0], s[qi][1]);
        __syncthreads();

        // O += P V (reduction over 32 keys)
#pragma unroll 4
        for (int k = 0; k < 32; ++k) {
            float4 bv = *(const float4*)&Vs[k][tx * 4];
#pragma unroll
            for (int qi = 0; qi < 4; qi++) {
                const float a = Ps[ty * 4 + qi][k];
                acc[qi][0] += a * bv.x;
                acc[qi][1] += a * bv.y;
                acc[qi][2] += a * bv.z;
                acc[qi][3] += a * bv.w;
            }
        }
        __syncthreads();
    }

    // epilogue: normalize and store to [b][t][h*64+d]
    float* Og = g_o + ((size_t)b * SEQ + q0) * KDIM + h * HDIM;
#pragma unroll
    for (int qi = 0; qi < 4; qi++) {
        const float inv = 1.0f / l_r[qi];
        float4 o = make_float4(acc[qi][0] * inv, acc[qi][1] * inv,
                               acc[qi][2] * inv, acc[qi][3] * inv);
        *(float4*)(Og + (size_t)(ty * 4 + qi) * KDIM + tx * 4) = o;
    }
}

// ---------------------------------------------------------------------------
extern "C" void kernel_launch(void* const* d_in, const int* in_sizes, int n_in,
                              void* d_out, int out_size)
{
    const float* x0      = (const float*)d_in[0];
    const int*   lengths = (const int*)d_in[1];   // int32 OR int64 buffer; decoded in-kernel
    const float* Wq      = (const float*)d_in[2];
    const float* Wk      = (const float*)d_in[3];
    const float* Wv      = (const float*)d_in[4];
    const float* Wu      = (const float*)d_in[5];
    const float* bu      = (const float*)d_in[6];
    float*       out     = (float*)d_out;

    // QKV projections (z = 0/1/2 selects Wq/Wk/Wv)
    {
        dim3 grid(KDIM / 128, MROWS / 128, 3);
        gemm_kernel<0><<<grid, 256>>>(x0, Wq, Wk, Wv, nullptr, nullptr);
    }
    // attention
    {
        dim3 grid(SEQ / 64, HEADS, BATCH);
        attn_kernel<<<grid, 256>>>(lengths);
    }
    // output projection + bias (reads g_o via device symbol)
    {
        dim3 grid(KDIM / 128, MROWS / 128, 1);
        float* oScratch;
        cudaGetSymbolAddress((void**)&oScratch, g_o);
        gemm_kernel<1><<<grid, 256>>>(oScratch, Wu, nullptr, nullptr, bu, out);
    }
}

// round 3
// speedup vs baseline: 2.7073x; 2.7073x over previous
#include <cuda_runtime.h>
#include <cuda_bf16.h>
#include <cstdint>

#define BATCH 4
#define SEQ   2048
#define KDIM  1024
#define HEADS 16
#define HDIM  64
#define MROWS (BATCH * SEQ)           // 8192
#define QK_SCALE 0.35355339059327373f // 64^(-1/4)

// Scratch (device globals — no allocations allowed)
__device__ float g_q[BATCH * HEADS * SEQ * HDIM];  // [b][h][t][d]
__device__ float g_k[BATCH * HEADS * SEQ * HDIM];
__device__ float g_v[BATCH * HEADS * SEQ * HDIM];
__device__ float g_o[BATCH * SEQ * KDIM];          // [b][t][h*64+d]

// ---------------------------------------------------------------------------
// tf32 helpers
// ---------------------------------------------------------------------------
__device__ __forceinline__ uint32_t f2tf(float f) {
    uint32_t u;
    asm("cvt.rna.tf32.f32 %0, %1;" : "=r"(u) : "f"(f));
    return u;
}
__device__ __forceinline__ float f2tf_f(float f) { return __uint_as_float(f2tf(f)); }

// D += A(16x8) * B(8x8);  A row-major, B col-major (i.e. B^T row-major).
__device__ __forceinline__ void mma_tf32(float c[4], const uint32_t a[4],
                                         uint32_t b0, uint32_t b1)
{
    asm volatile(
        "mma.sync.aligned.m16n8k8.row.col.f32.tf32.tf32.f32 "
        "{%0,%1,%2,%3}, {%4,%5,%6,%7}, {%8,%9}, {%0,%1,%2,%3};\n"
        : "+f"(c[0]), "+f"(c[1]), "+f"(c[2]), "+f"(c[3])
        : "r"(a[0]), "r"(a[1]), "r"(a[2]), "r"(a[3]), "r"(b0), "r"(b1));
}

// ---------------------------------------------------------------------------
// Robust length decoding (reference declares int64; JAX default materializes
// int32). lengths[b] >= 1 always; int64 little-endian buffer has zero words
// at i32 indices 1 and 3.
// ---------------------------------------------------------------------------
__device__ __forceinline__ int decode_length(const int* l32, int b)
{
    const bool is64 = (l32[1] == 0) && (l32[3] == 0);
    return is64 ? l32[2 * b] : l32[b];
}

// ---------------------------------------------------------------------------
// tf32 tensor-core GEMM: C[m,n] = sum_k A[m,k] * W[n,k]
// Tile 128x128, BK=16, 256 threads = 8 warps in 2(m) x 4(n); warp = 64m x 32n;
// per warp: 4 m-frags (16) x 4 n-frags (8), mma m16n8k8.
// MODE 0: QKV projection — blockIdx.z selects W/out; scaled scatter epilogue.
// MODE 1: output projection — bias add, plain row-major store.
// ---------------------------------------------------------------------------
template <int MODE>
__global__ void __launch_bounds__(256)
gemm_tc(const float* __restrict__ A,
        const float* __restrict__ W0,
        const float* __restrict__ W1,
        const float* __restrict__ W2,
        const float* __restrict__ bias,
        float* __restrict__ outPlain)
{
    const int tid  = threadIdx.x;
    const int warp = tid >> 5;
    const int lane = tid & 31;
    const int gid  = lane >> 2;
    const int tig  = lane & 3;
    const int warpM = (warp & 1) * 64;
    const int warpN = (warp >> 1) * 32;

    const float* W = W0;
    float* outQKV = nullptr;
    float scale = 1.0f;
    if (MODE == 0) {
        const int z = blockIdx.z;
        W      = (z == 0) ? W0 : (z == 1) ? W1 : W2;
        outQKV = (z == 0) ? g_q : (z == 1) ? g_k : g_v;
        scale  = (z == 2) ? 1.0f : QK_SCALE;
    }

    __shared__ __align__(16) float As[128][20];
    __shared__ __align__(16) float Bs[128][20];

    const int mBase = blockIdx.y * 128;
    const int nBase = blockIdx.x * 128;

    const int ldRow = tid >> 2;        // 0..63
    const int ldC   = (tid & 3) * 4;   // 0,4,8,12

    const float* Aptr = A + (size_t)(mBase + ldRow) * KDIM + ldC;
    const float* Bptr = W + (size_t)(nBase + ldRow) * KDIM + ldC;

    float4 ra0 = *(const float4*)(Aptr);
    float4 ra1 = *(const float4*)(Aptr + (size_t)64 * KDIM);
    float4 rb0 = *(const float4*)(Bptr);
    float4 rb1 = *(const float4*)(Bptr + (size_t)64 * KDIM);

    float acc[4][4][4];
#pragma unroll
    for (int i = 0; i < 4; i++)
#pragma unroll
        for (int j = 0; j < 4; j++)
#pragma unroll
            for (int c = 0; c < 4; c++) acc[i][j][c] = 0.0f;

#pragma unroll 1
    for (int kt = 0; kt < KDIM / 16; ++kt) {
        // stage (tf32-rounded)
        As[ldRow][ldC + 0] = f2tf_f(ra0.x);  As[ldRow][ldC + 1] = f2tf_f(ra0.y);
        As[ldRow][ldC + 2] = f2tf_f(ra0.z);  As[ldRow][ldC + 3] = f2tf_f(ra0.w);
        As[ldRow + 64][ldC + 0] = f2tf_f(ra1.x);  As[ldRow + 64][ldC + 1] = f2tf_f(ra1.y);
        As[ldRow + 64][ldC + 2] = f2tf_f(ra1.z);  As[ldRow + 64][ldC + 3] = f2tf_f(ra1.w);
        Bs[ldRow][ldC + 0] = f2tf_f(rb0.x);  Bs[ldRow][ldC + 1] = f2tf_f(rb0.y);
        Bs[ldRow][ldC + 2] = f2tf_f(rb0.z);  Bs[ldRow][ldC + 3] = f2tf_f(rb0.w);
        Bs[ldRow + 64][ldC + 0] = f2tf_f(rb1.x);  Bs[ldRow + 64][ldC + 1] = f2tf_f(rb1.y);
        Bs[ldRow + 64][ldC + 2] = f2tf_f(rb1.z);  Bs[ldRow + 64][ldC + 3] = f2tf_f(rb1.w);
        __syncthreads();

        if (kt < KDIM / 16 - 1) {
            Aptr += 16; Bptr += 16;
            ra0 = *(const float4*)(Aptr);
            ra1 = *(const float4*)(Aptr + (size_t)64 * KDIM);
            rb0 = *(const float4*)(Bptr);
            rb1 = *(const float4*)(Bptr + (size_t)64 * KDIM);
        }

#pragma unroll
        for (int ks = 0; ks < 2; ++ks) {
            const int k = ks * 8;
            uint32_t af[4][4];
#pragma unroll
            for (int mf = 0; mf < 4; mf++) {
                const int row = warpM + mf * 16 + gid;
                af[mf][0] = __float_as_uint(As[row][k + tig]);
                af[mf][1] = __float_as_uint(As[row + 8][k + tig]);
                af[mf][2] = __float_as_uint(As[row][k + tig + 4]);
                af[mf][3] = __float_as_uint(As[row + 8][k + tig + 4]);
            }
#pragma unroll
            for (int nf = 0; nf < 4; nf++) {
                const int col = warpN + nf * 8 + gid;
                const uint32_t b0 = __float_as_uint(Bs[col][k + tig]);
                const uint32_t b1 = __float_as_uint(Bs[col][k + tig + 4]);
#pragma unroll
                for (int mf = 0; mf < 4; mf++) mma_tf32(acc[mf][nf], af[mf], b0, b1);
            }
        }
        __syncthreads();
    }

    // epilogue
#pragma unroll
    for (int mf = 0; mf < 4; mf++) {
        const int r0 = mBase + warpM + mf * 16 + gid;
        const int r1 = r0 + 8;
#pragma unroll
        for (int nf = 0; nf < 4; nf++) {
            const int col = nBase + warpN + nf * 8 + 2 * tig;
            if (MODE == 0) {
                const int h = col >> 6, d = col & 63;
                const int b0_ = r0 >> 11, t0_ = r0 & (SEQ - 1);
                const int b1_ = r1 >> 11, t1_ = r1 & (SEQ - 1);
                float* p0 = outQKV + (((size_t)(b0_ * HEADS + h) * SEQ + t0_) << 6) + d;
                float* p1 = outQKV + (((size_t)(b1_ * HEADS + h) * SEQ + t1_) << 6) + d;
                *(float2*)p0 = make_float2(acc[mf][nf][0] * scale, acc[mf][nf][1] * scale);
                *(float2*)p1 = make_float2(acc[mf][nf][2] * scale, acc[mf][nf][3] * scale);
            } else {
                const float2 bv = *(const float2*)(bias + col);
                *(float2*)(outPlain + (size_t)r0 * KDIM + col) =
                    make_float2(acc[mf][nf][0] + bv.x, acc[mf][nf][1] + bv.y);
                *(float2*)(outPlain + (size_t)r1 * KDIM + col) =
                    make_float2(acc[mf][nf][2] + bv.x, acc[mf][nf][3] + bv.y);
            }
        }
    }
}

// ---------------------------------------------------------------------------
// Flash attention with tf32 mma.
// Block = 256 thr (8 warps), 128 queries per block, key tiles of 32.
// Warp w owns q rows [w*16, w*16+16). Q held in registers as A-frags.
// S = Q K^T (m16 x n32), softmax on C-frag layout, P -> smem, O += P V.
// ---------------------------------------------------------------------------
__global__ void __launch_bounds__(256)
attn_tc(const int* __restrict__ lengths32)
{
    const int b  = blockIdx.z;
    const int h  = blockIdx.y;
    const int q0 = blockIdx.x * 128;
    const int tid  = threadIdx.x;
    const int warp = tid >> 5;
    const int lane = tid & 31;
    const int gid  = lane >> 2;
    const int tig  = lane & 3;

    __shared__ __align__(16) float Ks[32][68];   // [key][d]
    __shared__ __align__(16) float Vs[64][36];   // [d][key]  (transposed)
    __shared__ __align__(16) float Ps[128][36];  // [q][key]

    const size_t headBase = (size_t)(b * HEADS + h) * SEQ * HDIM;
    const float* Qg = g_q + headBase + (size_t)q0 * HDIM;
    const float* Kg = g_k + headBase;
    const float* Vg = g_v + headBase;

    const int len = decode_length(lengths32, b);

    // Q fragments in registers (rows warp*16+gid, warp*16+gid+8)
    const int qr0 = warp * 16 + gid;
    const int qr1 = qr0 + 8;
    uint32_t aq[8][4];
#pragma unroll
    for (int ks = 0; ks < 8; ks++) {
        aq[ks][0] = f2tf(Qg[(size_t)qr0 * HDIM + ks * 8 + tig]);
        aq[ks][1] = f2tf(Qg[(size_t)qr1 * HDIM + ks * 8 + tig]);
        aq[ks][2] = f2tf(Qg[(size_t)qr0 * HDIM + ks * 8 + tig + 4]);
        aq[ks][3] = f2tf(Qg[(size_t)qr1 * HDIM + ks * 8 + tig + 4]);
    }

    float o[8][4];
#pragma unroll
    for (int nf = 0; nf < 8; nf++)
#pragma unroll
        for (int c = 0; c < 4; c++) o[nf][c] = 0.0f;
    float m0 = -1e30f, m1 = -1e30f, l0 = 0.0f, l1 = 0.0f;

#pragma unroll 1
    for (int kt = 0; kt < SEQ / 32; ++kt) {
        const int kb = kt * 32;

        // stage K (natural [key][d]) — tf32-rounded
        {
            const int row = tid >> 3;
            const int c   = (tid & 7) * 8;
            float4 v0 = *(const float4*)(Kg + (size_t)(kb + row) * HDIM + c);
            float4 v1 = *(const float4*)(Kg + (size_t)(kb + row) * HDIM + c + 4);
            Ks[row][c + 0] = f2tf_f(v0.x);  Ks[row][c + 1] = f2tf_f(v0.y);
            Ks[row][c + 2] = f2tf_f(v0.z);  Ks[row][c + 3] = f2tf_f(v0.w);
            Ks[row][c + 4] = f2tf_f(v1.x);  Ks[row][c + 5] = f2tf_f(v1.y);
            Ks[row][c + 6] = f2tf_f(v1.z);  Ks[row][c + 7] = f2tf_f(v1.w);
        }
        // stage V transposed ([d][key])
#pragma unroll
        for (int i = 0; i < 2; i++) {
            const int f = tid + i * 256;
            const int row = f >> 4;       // 0..31 (key)
            const int c4  = f & 15;       // d block
            float4 v = *(const float4*)(Vg + (size_t)(kb + row) * HDIM + c4 * 4);
            Vs[c4 * 4 + 0][row] = f2tf_f(v.x);
            Vs[c4 * 4 + 1][row] = f2tf_f(v.y);
            Vs[c4 * 4 + 2][row] = f2tf_f(v.z);
            Vs[c4 * 4 + 3][row] = f2tf_f(v.w);
        }
        __syncthreads();

        // S = Q K^T : 4 n-frags (8 keys each), k over 64 dims
        float s[4][4];
#pragma unroll
        for (int nf = 0; nf < 4; nf++)
#pragma unroll
            for (int c = 0; c < 4; c++) s[nf][c] = 0.0f;
#pragma unroll
        for (int ks = 0; ks < 8; ks++) {
#pragma unroll
            for (int nf = 0; nf < 4; nf++) {
                const uint32_t b0 = __float_as_uint(Ks[nf * 8 + gid][ks * 8 + tig]);
                const uint32_t b1 = __float_as_uint(Ks[nf * 8 + gid][ks * 8 + tig + 4]);
                mma_tf32(s[nf], aq[ks], b0, b1);
            }
        }

        // key-padding penalty (column-wise)
#pragma unroll
        for (int nf = 0; nf < 4; nf++) {
            const int k0 = kb + nf * 8 + 2 * tig;
            if (k0 >= len)     { s[nf][0] += -10000.0f; s[nf][2] += -10000.0f; }
            if (k0 + 1 >= len) { s[nf][1] += -10000.0f; s[nf][3] += -10000.0f; }
        }

        // online softmax (rows qr0, qr1; reduction across the quad)
        float rm0 = -1e30f, rm1 = -1e30f;
#pragma unroll
        for (int nf = 0; nf < 4; nf++) {
            rm0 = fmaxf(rm0, fmaxf(s[nf][0], s[nf][1]));
            rm1 = fmaxf(rm1, fmaxf(s[nf][2], s[nf][3]));
        }
        rm0 = fmaxf(rm0, __shfl_xor_sync(0xffffffffu, rm0, 1));
        rm0 = fmaxf(rm0, __shfl_xor_sync(0xffffffffu, rm0, 2));
        rm1 = fmaxf(rm1, __shfl_xor_sync(0xffffffffu, rm1, 1));
        rm1 = fmaxf(rm1, __shfl_xor_sync(0xffffffffu, rm1, 2));

        const float mn0 = fmaxf(m0, rm0);
        const float mn1 = fmaxf(m1, rm1);
        const float alpha0 = __expf(m0 - mn0);
        const float alpha1 = __expf(m1 - mn1);

        float rs0 = 0.0f, rs1 = 0.0f;
#pragma unroll
        for (int nf = 0; nf < 4; nf++) {
            const float p0 = __expf(s[nf][0] - mn0);
            const float p1 = __expf(s[nf][1] - mn0);
            const float p2 = __expf(s[nf][2] - mn1);
            const float p3 = __expf(s[nf][3] - mn1);
            rs0 += p0 + p1;
            rs1 += p2 + p3;
            *(float2*)&Ps[qr0][nf * 8 + 2 * tig] = make_float2(f2tf_f(p0), f2tf_f(p1));
            *(float2*)&Ps[qr1][nf * 8 + 2 * tig] = make_float2(f2tf_f(p2), f2tf_f(p3));
        }
        rs0 += __shfl_xor_sync(0xffffffffu, rs0, 1);
        rs0 += __shfl_xor_sync(0xffffffffu, rs0, 2);
        rs1 += __shfl_xor_sync(0xffffffffu, rs1, 1);
        rs1 += __shfl_xor_sync(0xffffffffu, rs1, 2);

        l0 = l0 * alpha0 + rs0;  m0 = mn0;
        l1 = l1 * alpha1 + rs1;  m1 = mn1;
#pragma unroll
        for (int nf = 0; nf < 8; nf++) {
            o[nf][0] *= alpha0;  o[nf][1] *= alpha0;
            o[nf][2] *= alpha1;  o[nf][3] *= alpha1;
        }
        __syncwarp();

        // O += P V : A = P (m16 x k32), B = V^T-in-smem (k32 x n64)
#pragma unroll
        for (int ks2 = 0; ks2 < 4; ks2++) {
            uint32_t pa[4];
            pa[0] = __float_as_uint(Ps[qr0][ks2 * 8 + tig]);
            pa[1] = __float_as_uint(Ps[qr1][ks2 * 8 + tig]);
            pa[2] = __float_as_uint(Ps[qr0][ks2 * 8 + tig + 4]);
            pa[3] = __float_as_uint(Ps[qr1][ks2 * 8 + tig + 4]);
#pragma unroll
            for (int nf = 0; nf < 8; nf++) {
                const uint32_t b0 = __float_as_uint(Vs[nf * 8 + gid][ks2 * 8 + tig]);
                const uint32_t b1 = __float_as_uint(Vs[nf * 8 + gid][ks2 * 8 + tig + 4]);
                mma_tf32(o[nf], pa, b0, b1);
            }
        }
        __syncthreads();
    }

    // epilogue: normalize, store to g_o[b][t][h*64+d]
    const float inv0 = 1.0f / l0;
    const float inv1 = 1.0f / l1;
    const int row0 = q0 + qr0;
    const int row1 = q0 + qr1;
#pragma unroll
    for (int nf = 0; nf < 8; nf++) {
        const int d = h * HDIM + nf * 8 + 2 * tig;
        *(float2*)(g_o + ((size_t)b * SEQ + row0) * KDIM + d) =
            make_float2(o[nf][0] * inv0, o[nf][1] * inv0);
        *(float2*)(g_o + ((size_t)b * SEQ + row1) * KDIM + d) =
            make_float2(o[nf][2] * inv1, o[nf][3] * inv1);
    }
}

// ---------------------------------------------------------------------------
extern "C" void kernel_launch(void* const* d_in, const int* in_sizes, int n_in,
                              void* d_out, int out_size)
{
    const float* x0      = (const float*)d_in[0];
    const int*   lengths = (const int*)d_in[1];   // int32 OR int64; decoded in-kernel
    const float* Wq      = (const float*)d_in[2];
    const float* Wk      = (const float*)d_in[3];
    const float* Wv      = (const float*)d_in[4];
    const float* Wu      = (const float*)d_in[5];
    const float* bu      = (const float*)d_in[6];
    float*       out     = (float*)d_out;

    // QKV projections
    {
        dim3 grid(KDIM / 128, MROWS / 128, 3);
        gemm_tc<0><<<grid, 256>>>(x0, Wq, Wk, Wv, nullptr, nullptr);
    }
    // attention
    {
        dim3 grid(SEQ / 128, HEADS, BATCH);
        attn_tc<<<grid, 256>>>(lengths);
    }
    // output projection + bias
    {
        dim3 grid(KDIM / 128, MROWS / 128, 1);
        float* oScratch;
        cudaGetSymbolAddress((void**)&oScratch, g_o);
        gemm_tc<1><<<grid, 256>>>(oScratch, Wu, nullptr, nullptr, bu, out);
    }
}

// round 4
// speedup vs baseline: 3.7233x; 1.3753x over previous
#include <cuda_runtime.h>
#include <cuda_bf16.h>
#include <cstdint>

#define BATCH 4
#define SEQ   2048
#define KDIM  1024
#define HEADS 16
#define HDIM  64
#define MROWS (BATCH * SEQ)           // 8192
#define QK_SCALE 0.35355339059327373f // 64^(-1/4)

// Scratch (device globals — no allocations allowed)
__device__ float g_q[BATCH * HEADS * SEQ * HDIM];  // [b][h][t][d]
__device__ float g_k[BATCH * HEADS * SEQ * HDIM];
__device__ float g_v[BATCH * HEADS * SEQ * HDIM];
__device__ float g_o[BATCH * SEQ * KDIM];          // [b][t][h*64+d]

// ---------------------------------------------------------------------------
__device__ __forceinline__ uint32_t f2tf(float f) {
    uint32_t u;
    asm("cvt.rna.tf32.f32 %0, %1;" : "=r"(u) : "f"(f));
    return u;
}
__device__ __forceinline__ float f2tf_f(float f) { return __uint_as_float(f2tf(f)); }

__device__ __forceinline__ void mma_tf32(float c[4], const uint32_t a[4],
                                         uint32_t b0, uint32_t b1)
{
    asm volatile(
        "mma.sync.aligned.m16n8k8.row.col.f32.tf32.tf32.f32 "
        "{%0,%1,%2,%3}, {%4,%5,%6,%7}, {%8,%9}, {%0,%1,%2,%3};\n"
        : "+f"(c[0]), "+f"(c[1]), "+f"(c[2]), "+f"(c[3])
        : "r"(a[0]), "r"(a[1]), "r"(a[2]), "r"(a[3]), "r"(b0), "r"(b1));
}

// int64-vs-int32 robust length decode (lengths[b] >= 1 always)
__device__ __forceinline__ int decode_length(const int* l32, int b)
{
    const bool is64 = (l32[1] == 0) && (l32[3] == 0);
    return is64 ? l32[2 * b] : l32[b];
}

// ---------------------------------------------------------------------------
// tf32 tensor-core GEMM with fragment-major smem.
// Tile 128x128, BK=16, 8 warps (2m x 4n), warp 64x32.
// Asf: [ks:2][tig:4 (stride 264 fl = 66 f4)][p:64 x float4], frag = 1 LDS.128
// Bsf: [ks:2][tig:4 (stride 264 fl = 132 f2)][col:128 x float2], frag = 1 LDS.64
// ---------------------------------------------------------------------------
template <int MODE>
__global__ void __launch_bounds__(256)
gemm_tc(const float* __restrict__ A,
        const float* __restrict__ W0,
        const float* __restrict__ W1,
        const float* __restrict__ W2,
        const float* __restrict__ bias,
        float* __restrict__ outPlain)
{
    const int tid  = threadIdx.x;
    const int warp = tid >> 5;
    const int lane = tid & 31;
    const int gid  = lane >> 2;
    const int tig  = lane & 3;
    const int warpM = (warp & 1) * 64;
    const int warpN = (warp >> 1) * 32;

    const float* W = W0;
    float* outQKV = nullptr;
    float scale = 1.0f;
    if (MODE == 0) {
        const int z = blockIdx.z;
        W      = (z == 0) ? W0 : (z == 1) ? W1 : W2;
        outQKV = (z == 0) ? g_q : (z == 1) ? g_k : g_v;
        scale  = (z == 2) ? 1.0f : QK_SCALE;
    }

    __shared__ __align__(16) float Asf[2112];
    __shared__ __align__(16) float Bsf[2112];

    const int mBase = blockIdx.y * 128;
    const int nBase = blockIdx.x * 128;

    const int ldRow = tid >> 2;        // 0..63
    const int ldC   = (tid & 3) * 4;   // 0,4,8,12

    const float* Aptr = A + (size_t)(mBase + ldRow) * KDIM + ldC;
    const float* Bptr = W + (size_t)(nBase + ldRow) * KDIM + ldC;

    float4 ra0 = *(const float4*)(Aptr);
    float4 ra1 = *(const float4*)(Aptr + (size_t)64 * KDIM);
    float4 rb0 = *(const float4*)(Bptr);
    float4 rb1 = *(const float4*)(Bptr + (size_t)64 * KDIM);

    // staging constants for this thread
    const int p0     = ((ldRow >> 4) << 3) | (ldRow & 7);  // 0..31 (row+64 -> p0+32)
    const int rowbit = (ldRow >> 3) & 1;

    float acc[4][4][4];
#pragma unroll
    for (int i = 0; i < 4; i++)
#pragma unroll
        for (int j = 0; j < 4; j++)
#pragma unroll
            for (int c = 0; c < 4; c++) acc[i][j][c] = 0.0f;

#pragma unroll 1
    for (int kt = 0; kt < KDIM / 16; ++kt) {
#define STG(J, AX0, AX1, BX0, BX1)                                   \
        {                                                            \
            const int c_  = ldC + (J);                               \
            const int ks_ = c_ >> 3;                                 \
            const int w_  = c_ & 7;                                  \
            const int tg_ = w_ & 3;                                  \
            const int hf_ = w_ >> 2;                                 \
            float* ap_ = Asf + ks_ * 1056 + tg_ * 264;               \
            float* bp_ = Bsf + ks_ * 1056 + tg_ * 264;               \
            ap_[p0 * 4 + hf_ * 2 + rowbit]        = f2tf_f(AX0);     \
            ap_[(p0 + 32) * 4 + hf_ * 2 + rowbit] = f2tf_f(AX1);     \
            bp_[ldRow * 2 + hf_]                  = f2tf_f(BX0);     \
            bp_[(ldRow + 64) * 2 + hf_]           = f2tf_f(BX1);     \
        }
        STG(0, ra0.x, ra1.x, rb0.x, rb1.x)
        STG(1, ra0.y, ra1.y, rb0.y, rb1.y)
        STG(2, ra0.z, ra1.z, rb0.z, rb1.z)
        STG(3, ra0.w, ra1.w, rb0.w, rb1.w)
#undef STG
        __syncthreads();

        if (kt < KDIM / 16 - 1) {
            Aptr += 16; Bptr += 16;
            ra0 = *(const float4*)(Aptr);
            ra1 = *(const float4*)(Aptr + (size_t)64 * KDIM);
            rb0 = *(const float4*)(Bptr);
            rb1 = *(const float4*)(Bptr + (size_t)64 * KDIM);
        }

#pragma unroll
        for (int ks = 0; ks < 2; ++ks) {
            const float* ak = Asf + ks * 1056 + tig * 264;
            const float* bk = Bsf + ks * 1056 + tig * 264;
            uint4 af[4];
            uint2 bf[4];
#pragma unroll
            for (int mf = 0; mf < 4; mf++)
                af[mf] = *(const uint4*)(ak + ((warpM >> 1) + mf * 8 + gid) * 4);
#pragma unroll
            for (int nf = 0; nf < 4; nf++)
                bf[nf] = *(const uint2*)(bk + (warpN + nf * 8 + gid) * 2);
#pragma unroll
            for (int nf = 0; nf < 4; nf++)
#pragma unroll
                for (int mf = 0; mf < 4; mf++)
                    mma_tf32(acc[mf][nf], (const uint32_t*)&af[mf], bf[nf].x, bf[nf].y);
        }
        __syncthreads();
    }

    // epilogue (C-frag: rows gid, gid+8; cols 2tig, 2tig+1 per 8-col group)
#pragma unroll
    for (int mf = 0; mf < 4; mf++) {
        const int r0 = mBase + warpM + mf * 16 + gid;
        const int r1 = r0 + 8;
#pragma unroll
        for (int nf = 0; nf < 4; nf++) {
            const int col = nBase + warpN + nf * 8 + 2 * tig;
            if (MODE == 0) {
                const int h = col >> 6, d = col & 63;
                const int b0_ = r0 >> 11, t0_ = r0 & (SEQ - 1);
                const int b1_ = r1 >> 11, t1_ = r1 & (SEQ - 1);
                float* q0p = outQKV + (((size_t)(b0_ * HEADS + h) * SEQ + t0_) << 6) + d;
                float* q1p = outQKV + (((size_t)(b1_ * HEADS + h) * SEQ + t1_) << 6) + d;
                *(float2*)q0p = make_float2(acc[mf][nf][0] * scale, acc[mf][nf][1] * scale);
                *(float2*)q1p = make_float2(acc[mf][nf][2] * scale, acc[mf][nf][3] * scale);
            } else {
                const float2 bv = *(const float2*)(bias + col);
                *(float2*)(outPlain + (size_t)r0 * KDIM + col) =
                    make_float2(acc[mf][nf][0] + bv.x, acc[mf][nf][1] + bv.y);
                *(float2*)(outPlain + (size_t)r1 * KDIM + col) =
                    make_float2(acc[mf][nf][2] + bv.x, acc[mf][nf][3] + bv.y);
            }
        }
    }
}

// ---------------------------------------------------------------------------
// Flash attention, tf32 mma, fragment-major K/V/P smem, exact masked-tile skip.
// Block = 256 thr (8 warps), 128 queries, key tiles of 32.
// Ksf: [ks:8 (stride 292 fl)][tig (stride 72 fl)][key x float2]
// Vsf: [ks2:4 (stride 546 fl)][tig (stride 136 fl)][d x float2]
// Psf: per-warp [ks2:4 (160 fl)][tig (40 fl)][gid x float4]
// ---------------------------------------------------------------------------
__global__ void __launch_bounds__(256)
attn_tc(const int* __restrict__ lengths32)
{
    const int b  = blockIdx.z;
    const int h  = blockIdx.y;
    const int q0 = blockIdx.x * 128;
    const int tid  = threadIdx.x;
    const int warp = tid >> 5;
    const int lane = tid & 31;
    const int gid  = lane >> 2;
    const int tig  = lane & 3;

    __shared__ __align__(16) float Ksf[8 * 292];   // 9344 B
    __shared__ __align__(16) float Vsf[4 * 546];   // 8736 B
    __shared__ __align__(16) float Psf[8 * 640];   // 20480 B

    const size_t headBase = (size_t)(b * HEADS + h) * SEQ * HDIM;
    const float* Qg = g_q + headBase + (size_t)q0 * HDIM;
    const float* Kg = g_k + headBase;
    const float* Vg = g_v + headBase;

    const int len = decode_length(lengths32, b);
    const int ktEnd = (len + 31) >> 5;   // masked tiles contribute exactly 0

    // Q fragments in registers (rows qr0 = warp*16+gid, qr1 = qr0+8)
    const int qr0 = warp * 16 + gid;
    const int qr1 = qr0 + 8;
    uint32_t aq[8][4];
#pragma unroll
    for (int ks = 0; ks < 8; ks++) {
        aq[ks][0] = f2tf(Qg[(size_t)qr0 * HDIM + ks * 8 + tig]);
        aq[ks][1] = f2tf(Qg[(size_t)qr1 * HDIM + ks * 8 + tig]);
        aq[ks][2] = f2tf(Qg[(size_t)qr0 * HDIM + ks * 8 + tig + 4]);
        aq[ks][3] = f2tf(Qg[(size_t)qr1 * HDIM + ks * 8 + tig + 4]);
    }

    float o[8][4];
#pragma unroll
    for (int nf = 0; nf < 8; nf++)
#pragma unroll
        for (int c = 0; c < 4; c++) o[nf][c] = 0.0f;
    float m0 = -1e30f, m1 = -1e30f, l0 = 0.0f, l1 = 0.0f;

    float* const pw = Psf + warp * 640 + gid * 4;   // P writer base (this warp)

#pragma unroll 1
    for (int kt = 0; kt < ktEnd; ++kt) {
        const int kb = kt * 32;

        // stage K: warp w handles d-slab [w*8, w*8+8) of all 32 keys
        {
            const float* src = Kg + (size_t)(kb + lane) * HDIM + warp * 8;
            float4 v0 = *(const float4*)(src);
            float4 v1 = *(const float4*)(src + 4);
            float* kp = Ksf + warp * 292 + lane * 2;
            kp[0 * 72 + 0] = f2tf_f(v0.x);  kp[1 * 72 + 0] = f2tf_f(v0.y);
            kp[2 * 72 + 0] = f2tf_f(v0.z);  kp[3 * 72 + 0] = f2tf_f(v0.w);
            kp[0 * 72 + 1] = f2tf_f(v1.x);  kp[1 * 72 + 1] = f2tf_f(v1.y);
            kp[2 * 72 + 1] = f2tf_f(v1.z);  kp[3 * 72 + 1] = f2tf_f(v1.w);
        }
        // stage V: warp w handles d-slab [w*8, w*8+8) of all 32 keys
        {
            const float* src = Vg + (size_t)(kb + lane) * HDIM + warp * 8;
            float4 v0 = *(const float4*)(src);
            float4 v1 = *(const float4*)(src + 4);
            const int ks2 = lane >> 3;
            const int tg  = lane & 3;
            const int hf  = (lane >> 2) & 1;
            float* vp = Vsf + ks2 * 546 + tg * 136 + hf;
            const int d0 = warp * 8;
            vp[(d0 + 0) * 2] = f2tf_f(v0.x);  vp[(d0 + 1) * 2] = f2tf_f(v0.y);
            vp[(d0 + 2) * 2] = f2tf_f(v0.z);  vp[(d0 + 3) * 2] = f2tf_f(v0.w);
            vp[(d0 + 4) * 2] = f2tf_f(v1.x);  vp[(d0 + 5) * 2] = f2tf_f(v1.y);
            vp[(d0 + 6) * 2] = f2tf_f(v1.z);  vp[(d0 + 7) * 2] = f2tf_f(v1.w);
        }
        __syncthreads();

        // S = Q K^T : 4 n-frags of 8 keys, k over 64 dims
        float s[4][4];
#pragma unroll
        for (int nf = 0; nf < 4; nf++)
#pragma unroll
            for (int c = 0; c < 4; c++) s[nf][c] = 0.0f;
#pragma unroll
        for (int ks = 0; ks < 8; ks++) {
            const float* kk = Ksf + ks * 292 + tig * 72;
#pragma unroll
            for (int nf = 0; nf < 4; nf++) {
                const uint2 bf = *(const uint2*)(kk + (nf * 8 + gid) * 2);
                mma_tf32(s[nf], aq[ks], bf.x, bf.y);
            }
        }

        // key-padding penalty (only the boundary tile needs it)
        if (kb + 32 > len) {
#pragma unroll
            for (int nf = 0; nf < 4; nf++) {
                const int k0 = kb + nf * 8 + 2 * tig;
                if (k0 >= len)     { s[nf][0] += -10000.0f; s[nf][2] += -10000.0f; }
                if (k0 + 1 >= len) { s[nf][1] += -10000.0f; s[nf][3] += -10000.0f; }
            }
        }

        // online softmax (rows qr0, qr1; reduce across quad lanes)
        float rm0 = -1e30f, rm1 = -1e30f;
#pragma unroll
        for (int nf = 0; nf < 4; nf++) {
            rm0 = fmaxf(rm0, fmaxf(s[nf][0], s[nf][1]));
            rm1 = fmaxf(rm1, fmaxf(s[nf][2], s[nf][3]));
        }
        rm0 = fmaxf(rm0, __shfl_xor_sync(0xffffffffu, rm0, 1));
        rm0 = fmaxf(rm0, __shfl_xor_sync(0xffffffffu, rm0, 2));
        rm1 = fmaxf(rm1, __shfl_xor_sync(0xffffffffu, rm1, 1));
        rm1 = fmaxf(rm1, __shfl_xor_sync(0xffffffffu, rm1, 2));

        const float mn0 = fmaxf(m0, rm0);
        const float mn1 = fmaxf(m1, rm1);
        const float alpha0 = __expf(m0 - mn0);
        const float alpha1 = __expf(m1 - mn1);

        float rs0 = 0.0f, rs1 = 0.0f;
#pragma unroll
        for (int nf = 0; nf < 4; nf++) {
            const float p0v = __expf(s[nf][0] - mn0);  // qr0, col 2tig
            const float p1v = __expf(s[nf][1] - mn0);  // qr0, col 2tig+1
            const float p2v = __expf(s[nf][2] - mn1);  // qr1, col 2tig
            const float p3v = __expf(s[nf][3] - mn1);  // qr1, col 2tig+1
            rs0 += p0v + p1v;
            rs1 += p2v + p3v;
            // write to fragment-major Psf
            float* pn = pw + nf * 160;
            {
                const int c = 2 * tig;
                const int tt = c & 3, hf = c >> 2;
                pn[tt * 40 + hf * 2 + 0] = f2tf_f(p0v);
                pn[tt * 40 + hf * 2 + 1] = f2tf_f(p2v);
            }
            {
                const int c = 2 * tig + 1;
                const int tt = c & 3, hf = c >> 2;
                pn[tt * 40 + hf * 2 + 0] = f2tf_f(p1v);
                pn[tt * 40 + hf * 2 + 1] = f2tf_f(p3v);
            }
        }
        rs0 += __shfl_xor_sync(0xffffffffu, rs0, 1);
        rs0 += __shfl_xor_sync(0xffffffffu, rs0, 2);
        rs1 += __shfl_xor_sync(0xffffffffu, rs1, 1);
        rs1 += __shfl_xor_sync(0xffffffffu, rs1, 2);

        l0 = l0 * alpha0 + rs0;  m0 = mn0;
        l1 = l1 * alpha1 + rs1;  m1 = mn1;
#pragma unroll
        for (int nf = 0; nf < 8; nf++) {
            o[nf][0] *= alpha0;  o[nf][1] *= alpha0;
            o[nf][2] *= alpha1;  o[nf][3] *= alpha1;
        }
        __syncwarp();

        // O += P V
#pragma unroll
        for (int ks2 = 0; ks2 < 4; ks2++) {
            const uint4 pa = *(const uint4*)(Psf + warp * 640 + ks2 * 160 + tig * 40 + gid * 4);
            const float* vk = Vsf + ks2 * 546 + tig * 136;
#pragma unroll
            for (int nf = 0; nf < 8; nf++) {
                const uint2 bf = *(const uint2*)(vk + (nf * 8 + gid) * 2);
                mma_tf32(o[nf], (const uint32_t*)&pa, bf.x, bf.y);
            }
        }
        __syncthreads();
    }

    // epilogue: normalize, store to g_o[b][t][h*64+d]
    const float inv0 = 1.0f / l0;
    const float inv1 = 1.0f / l1;
    const int row0 = q0 + qr0;
    const int row1 = q0 + qr1;
#pragma unroll
    for (int nf = 0; nf < 8; nf++) {
        const int d = h * HDIM + nf * 8 + 2 * tig;
        *(float2*)(g_o + ((size_t)b * SEQ + row0) * KDIM + d) =
            make_float2(o[nf][0] * inv0, o[nf][1] * inv0);
        *(float2*)(g_o + ((size_t)b * SEQ + row1) * KDIM + d) =
            make_float2(o[nf][2] * inv1, o[nf][3] * inv1);
    }
}

// ---------------------------------------------------------------------------
extern "C" void kernel_launch(void* const* d_in, const int* in_sizes, int n_in,
                              void* d_out, int out_size)
{
    const float* x0      = (const float*)d_in[0];
    const int*   lengths = (const int*)d_in[1];   // int32 OR int64; decoded in-kernel
    const float* Wq      = (const float*)d_in[2];
    const float* Wk      = (const float*)d_in[3];
    const float* Wv      = (const float*)d_in[4];
    const float* Wu      = (const float*)d_in[5];
    const float* bu      = (const float*)d_in[6];
    float*       out     = (float*)d_out;

    // QKV projections
    {
        dim3 grid(KDIM / 128, MROWS / 128, 3);
        gemm_tc<0><<<grid, 256>>>(x0, Wq, Wk, Wv, nullptr, nullptr);
    }
    // attention
    {
        dim3 grid(SEQ / 128, HEADS, BATCH);
        attn_tc<<<grid, 256>>>(lengths);
    }
    // output projection + bias
    {
        dim3 grid(KDIM / 128, MROWS / 128, 1);
        float* oScratch;
        cudaGetSymbolAddress((void**)&oScratch, g_o);
        gemm_tc<1><<<grid, 256>>>(oScratch, Wu, nullptr, nullptr, bu, out);
    }
}

// round 6
// speedup vs baseline: 4.0356x; 1.0839x over previous
#include <cuda_runtime.h>
#include <cuda_bf16.h>
#include <cstdint>

#define BATCH 4
#define SEQ   2048
#define KDIM  1024
#define HEADS 16
#define HDIM  64
#define MROWS (BATCH * SEQ)           // 8192
#define QK_SCALE 0.35355339059327373f // 64^(-1/4)

// Scratch (device globals — no allocations allowed)
__device__ float g_q[BATCH * HEADS * SEQ * HDIM];  // [b][h][t][d]
__device__ float g_k[BATCH * HEADS * SEQ * HDIM];
__device__ float g_v[BATCH * HEADS * SEQ * HDIM];
__device__ float g_o[BATCH * SEQ * KDIM];          // [b][t][h*64+d]

// ---------------------------------------------------------------------------
__device__ __forceinline__ uint32_t f2tf(float f) {
    uint32_t u;
    asm("cvt.rna.tf32.f32 %0, %1;" : "=r"(u) : "f"(f));
    return u;
}
__device__ __forceinline__ float f2tf_f(float f) { return __uint_as_float(f2tf(f)); }

__device__ __forceinline__ void mma_tf32(float c[4], const uint32_t a[4],
                                         uint32_t b0, uint32_t b1)
{
    asm volatile(
        "mma.sync.aligned.m16n8k8.row.col.f32.tf32.tf32.f32 "
        "{%0,%1,%2,%3}, {%4,%5,%6,%7}, {%8,%9}, {%0,%1,%2,%3};\n"
        : "+f"(c[0]), "+f"(c[1]), "+f"(c[2]), "+f"(c[3])
        : "r"(a[0]), "r"(a[1]), "r"(a[2]), "r"(a[3]), "r"(b0), "r"(b1));
}

// int64-vs-int32 robust length decode (lengths[b] >= 1 always)
__device__ __forceinline__ int decode_length(const int* l32, int b)
{
    const bool is64 = (l32[1] == 0) && (l32[3] == 0);
    return is64 ? l32[2 * b] : l32[b];
}

// ---------------------------------------------------------------------------
// tf32 tensor-core GEMM, fragment-major smem, DOUBLE-BUFFERED (1 sync/tile).
// Tile 128x128, BK=16, 8 warps (2m x 4n), warp 64x32.
// Stage layout (floats): Asf = sm + s*4224 (2112 fl), Bsf = Asf + 2112.
//   Asf: [ks:2][tig:4 (264 fl)][p:64 x float4]  -> A-frag = 1 LDS.128
//   Bsf: [ks:2][tig:4 (264 fl)][col:128 x float2] -> B-frag = 1 LDS.64
// Dynamic smem: 2 * 4224 * 4 = 33792 B.
// ---------------------------------------------------------------------------
#define GEMM_SMEM 33792

template <int MODE>
__global__ void __launch_bounds__(256)
gemm_tc(const float* __restrict__ A,
        const float* __restrict__ W0,
        const float* __restrict__ W1,
        const float* __restrict__ W2,
        const float* __restrict__ bias,
        float* __restrict__ outPlain)
{
    extern __shared__ __align__(16) float sm[];

    const int tid  = threadIdx.x;
    const int warp = tid >> 5;
    const int lane = tid & 31;
    const int gid  = lane >> 2;
    const int tig  = lane & 3;
    const int warpM = (warp & 1) * 64;
    const int warpN = (warp >> 1) * 32;

    const float* W = W0;
    float* outQKV = nullptr;
    float scale = 1.0f;
    if (MODE == 0) {
        const int z = blockIdx.z;
        W      = (z == 0) ? W0 : (z == 1) ? W1 : W2;
        outQKV = (z == 0) ? g_q : (z == 1) ? g_k : g_v;
        scale  = (z == 2) ? 1.0f : QK_SCALE;
    }

    const int mBase = blockIdx.y * 128;
    const int nBase = blockIdx.x * 128;

    const int ldRow = tid >> 2;        // 0..63
    const int ldC   = (tid & 3) * 4;   // 0,4,8,12

    const float* Aptr = A + (size_t)(mBase + ldRow) * KDIM + ldC;
    const float* Bptr = W + (size_t)(nBase + ldRow) * KDIM + ldC;

    // staging constants
    const int p0     = ((ldRow >> 4) << 3) | (ldRow & 7);
    const int rowbit = (ldRow >> 3) & 1;

    float4 ra0 = *(const float4*)(Aptr);
    float4 ra1 = *(const float4*)(Aptr + (size_t)64 * KDIM);
    float4 rb0 = *(const float4*)(Bptr);
    float4 rb1 = *(const float4*)(Bptr + (size_t)64 * KDIM);

#define STG_TILE(DST)                                                 \
    {                                                                 \
        float* Asf_ = (DST);                                          \
        float* Bsf_ = (DST) + 2112;                                   \
        _Pragma("unroll")                                             \
        for (int j_ = 0; j_ < 4; j_++) {                              \
            const int c_  = ldC + j_;                                 \
            const int ks_ = c_ >> 3;                                  \
            const int w_  = c_ & 7;                                   \
            const int tg_ = w_ & 3;                                   \
            const int hf_ = w_ >> 2;                                  \
            float* ap_ = Asf_ + ks_ * 1056 + tg_ * 264;               \
            float* bp_ = Bsf_ + ks_ * 1056 + tg_ * 264;               \
            const float ax0 = (j_ == 0) ? ra0.x : (j_ == 1) ? ra0.y : (j_ == 2) ? ra0.z : ra0.w; \
            const float ax1 = (j_ == 0) ? ra1.x : (j_ == 1) ? ra1.y : (j_ == 2) ? ra1.z : ra1.w; \
            const float bx0 = (j_ == 0) ? rb0.x : (j_ == 1) ? rb0.y : (j_ == 2) ? rb0.z : rb0.w; \
            const float bx1 = (j_ == 0) ? rb1.x : (j_ == 1) ? rb1.y : (j_ == 2) ? rb1.z : rb1.w; \
            ap_[p0 * 4 + hf_ * 2 + rowbit]        = f2tf_f(ax0);      \
            ap_[(p0 + 32) * 4 + hf_ * 2 + rowbit] = f2tf_f(ax1);      \
            bp_[ldRow * 2 + hf_]                  = f2tf_f(bx0);      \
            bp_[(ldRow + 64) * 2 + hf_]           = f2tf_f(bx1);      \
        }                                                             \
    }

    // stage tile 0 into stage 0
    STG_TILE(sm)
    __syncthreads();

    float acc[4][4][4];
#pragma unroll
    for (int i = 0; i < 4; i++)
#pragma unroll
        for (int j = 0; j < 4; j++)
#pragma unroll
            for (int c = 0; c < 4; c++) acc[i][j][c] = 0.0f;

#pragma unroll 1
    for (int kt = 0; kt < KDIM / 16; ++kt) {
        const int s = kt & 1;
        const float* Asf = sm + s * 4224;
        const float* Bsf = Asf + 2112;

        const bool more = (kt < KDIM / 16 - 1);
        if (more) {               // issue prefetch LDGs early
            Aptr += 16; Bptr += 16;
            ra0 = *(const float4*)(Aptr);
            ra1 = *(const float4*)(Aptr + (size_t)64 * KDIM);
            rb0 = *(const float4*)(Bptr);
            rb1 = *(const float4*)(Bptr + (size_t)64 * KDIM);
        }

        // compute on stage s
#pragma unroll
        for (int ks = 0; ks < 2; ++ks) {
            const float* ak = Asf + ks * 1056 + tig * 264;
            const float* bk = Bsf + ks * 1056 + tig * 264;
            uint4 af[4];
            uint2 bf[4];
#pragma unroll
            for (int mf = 0; mf < 4; mf++)
                af[mf] = *(const uint4*)(ak + ((warpM >> 1) + mf * 8 + gid) * 4);
#pragma unroll
            for (int nf = 0; nf < 4; nf++)
                bf[nf] = *(const uint2*)(bk + (warpN + nf * 8 + gid) * 2);
#pragma unroll
            for (int nf = 0; nf < 4; nf++)
#pragma unroll
                for (int mf = 0; mf < 4; mf++)
                    mma_tf32(acc[mf][nf], (const uint32_t*)&af[mf], bf[nf].x, bf[nf].y);
        }

        if (more) STG_TILE(sm + (s ^ 1) * 4224)   // stage kt+1 -> other buffer
        __syncthreads();
    }
#undef STG_TILE

    // epilogue (C-frag: rows gid, gid+8; cols 2tig, 2tig+1 per 8-col group)
#pragma unroll
    for (int mf = 0; mf < 4; mf++) {
        const int r0 = mBase + warpM + mf * 16 + gid;
        const int r1 = r0 + 8;
#pragma unroll
        for (int nf = 0; nf < 4; nf++) {
            const int col = nBase + warpN + nf * 8 + 2 * tig;
            if (MODE == 0) {
                const int h = col >> 6, d = col & 63;
                const int b0_ = r0 >> 11, t0_ = r0 & (SEQ - 1);
                const int b1_ = r1 >> 11, t1_ = r1 & (SEQ - 1);
                float* q0p = outQKV + (((size_t)(b0_ * HEADS + h) * SEQ + t0_) << 6) + d;
                float* q1p = outQKV + (((size_t)(b1_ * HEADS + h) * SEQ + t1_) << 6) + d;
                *(float2*)q0p = make_float2(acc[mf][nf][0] * scale, acc[mf][nf][1] * scale);
                *(float2*)q1p = make_float2(acc[mf][nf][2] * scale, acc[mf][nf][3] * scale);
            } else {
                const float2 bv = *(const float2*)(bias + col);
                *(float2*)(outPlain + (size_t)r0 * KDIM + col) =
                    make_float2(acc[mf][nf][0] + bv.x, acc[mf][nf][1] + bv.y);
                *(float2*)(outPlain + (size_t)r1 * KDIM + col) =
                    make_float2(acc[mf][nf][2] + bv.x, acc[mf][nf][3] + bv.y);
            }
        }
    }
}

// ---------------------------------------------------------------------------
// Flash attention, tf32 mma.sync, fragment-major K/V/P smem, masked-tile skip,
// DOUBLE-BUFFERED K/V stages (1 block barrier per key tile).
// Dynamic smem layout (floats):
//   K stage s: sm + s*2336              (2336 fl each)
//   V stage s: sm + 4672 + s*2184      (2184 fl each)
//   P (per-warp, single): sm + 9040    (5120 fl)
// Total 14160 floats = 56640 B.
// ---------------------------------------------------------------------------
#define ATTN_SMEM 56640

__global__ void __launch_bounds__(256)
attn_tc(const int* __restrict__ lengths32)
{
    extern __shared__ __align__(16) float sm[];

    const int b  = blockIdx.z;
    const int h  = blockIdx.y;
    const int q0 = blockIdx.x * 128;
    const int tid  = threadIdx.x;
    const int warp = tid >> 5;
    const int lane = tid & 31;
    const int gid  = lane >> 2;
    const int tig  = lane & 3;

    float* const Psf = sm + 9040;

    const size_t headBase = (size_t)(b * HEADS + h) * SEQ * HDIM;
    const float* Qg = g_q + headBase + (size_t)q0 * HDIM;
    const float* Kg = g_k + headBase;
    const float* Vg = g_v + headBase;

    const int len = decode_length(lengths32, b);
    const int ktEnd = (len + 31) >> 5;   // masked tiles contribute exactly 0

    // Q fragments in registers (rows qr0 = warp*16+gid, qr1 = qr0+8)
    const int qr0 = warp * 16 + gid;
    const int qr1 = qr0 + 8;
    uint32_t aq[8][4];
#pragma unroll
    for (int ks = 0; ks < 8; ks++) {
        aq[ks][0] = f2tf(Qg[(size_t)qr0 * HDIM + ks * 8 + tig]);
        aq[ks][1] = f2tf(Qg[(size_t)qr1 * HDIM + ks * 8 + tig]);
        aq[ks][2] = f2tf(Qg[(size_t)qr0 * HDIM + ks * 8 + tig + 4]);
        aq[ks][3] = f2tf(Qg[(size_t)qr1 * HDIM + ks * 8 + tig + 4]);
    }

    float o[8][4];
#pragma unroll
    for (int nf = 0; nf < 8; nf++)
#pragma unroll
        for (int c = 0; c < 4; c++) o[nf][c] = 0.0f;
    float m0 = -1e30f, m1 = -1e30f, l0 = 0.0f, l1 = 0.0f;

    float* const pw = Psf + warp * 640 + gid * 4;

    // staging constants (thread roles identical to round 4)
    const int v_ks2 = lane >> 3;
    const int v_tg  = lane & 3;
    const int v_hf  = (lane >> 2) & 1;

    // prefetch registers
    float4 kv0, kv1, vv0, vv1;
#define LOAD_TILE(KB)                                                      \
    {                                                                      \
        const float* ksrc = Kg + (size_t)((KB) + lane) * HDIM + warp * 8;  \
        kv0 = *(const float4*)(ksrc);                                      \
        kv1 = *(const float4*)(ksrc + 4);                                  \
        const float* vsrc = Vg + (size_t)((KB) + lane) * HDIM + warp * 8;  \
        vv0 = *(const float4*)(vsrc);                                      \
        vv1 = *(const float4*)(vsrc + 4);                                  \
    }
#define STORE_TILE(S)                                                      \
    {                                                                      \
        float* Ksf_ = sm + (S) * 2336;                                     \
        float* Vsf_ = sm + 4672 + (S) * 2184;                              \
        float* kp = Ksf_ + warp * 292 + lane * 2;                          \
        kp[0 * 72 + 0] = f2tf_f(kv0.x);  kp[1 * 72 + 0] = f2tf_f(kv0.y);   \
        kp[2 * 72 + 0] = f2tf_f(kv0.z);  kp[3 * 72 + 0] = f2tf_f(kv0.w);   \
        kp[0 * 72 + 1] = f2tf_f(kv1.x);  kp[1 * 72 + 1] = f2tf_f(kv1.y);   \
        kp[2 * 72 + 1] = f2tf_f(kv1.z);  kp[3 * 72 + 1] = f2tf_f(kv1.w);   \
        float* vp = Vsf_ + v_ks2 * 546 + v_tg * 136 + v_hf;                \
        const int d0 = warp * 8;                                           \
        vp[(d0 + 0) * 2] = f2tf_f(vv0.x);  vp[(d0 + 1) * 2] = f2tf_f(vv0.y); \
        vp[(d0 + 2) * 2] = f2tf_f(vv0.z);  vp[(d0 + 3) * 2] = f2tf_f(vv0.w); \
        vp[(d0 + 4) * 2] = f2tf_f(vv1.x);  vp[(d0 + 5) * 2] = f2tf_f(vv1.y); \
        vp[(d0 + 6) * 2] = f2tf_f(vv1.z);  vp[(d0 + 7) * 2] = f2tf_f(vv1.w); \
    }

    LOAD_TILE(0)
    STORE_TILE(0)
    __syncthreads();

#pragma unroll 1
    for (int kt = 0; kt < ktEnd; ++kt) {
        const int s = kt & 1;
        const int kb = kt * 32;
        const bool more = (kt + 1 < ktEnd);

        if (more) LOAD_TILE(kb + 32)   // LDGs issued, consumed after compute

        const float* Ksf = sm + s * 2336;
        const float* Vsf = sm + 4672 + s * 2184;

        // S = Q K^T : 4 n-frags of 8 keys, k over 64 dims
        float sfr[4][4];
#pragma unroll
        for (int nf = 0; nf < 4; nf++)
#pragma unroll
            for (int c = 0; c < 4; c++) sfr[nf][c] = 0.0f;
#pragma unroll
        for (int ks = 0; ks < 8; ks++) {
            const float* kk = Ksf + ks * 292 + tig * 72;
#pragma unroll
            for (int nf = 0; nf < 4; nf++) {
                const uint2 bf = *(const uint2*)(kk + (nf * 8 + gid) * 2);
                mma_tf32(sfr[nf], aq[ks], bf.x, bf.y);
            }
        }

        // key-padding penalty (boundary tile only)
        if (kb + 32 > len) {
#pragma unroll
            for (int nf = 0; nf < 4; nf++) {
                const int k0 = kb + nf * 8 + 2 * tig;
                if (k0 >= len)     { sfr[nf][0] += -10000.0f; sfr[nf][2] += -10000.0f; }
                if (k0 + 1 >= len) { sfr[nf][1] += -10000.0f; sfr[nf][3] += -10000.0f; }
            }
        }

        // online softmax (rows qr0, qr1; reduce across quad lanes)
        float rm0 = -1e30f, rm1 = -1e30f;
#pragma unroll
        for (int nf = 0; nf < 4; nf++) {
            rm0 = fmaxf(rm0, fmaxf(sfr[nf][0], sfr[nf][1]));
            rm1 = fmaxf(rm1, fmaxf(sfr[nf][2], sfr[nf][3]));
        }
        rm0 = fmaxf(rm0, __shfl_xor_sync(0xffffffffu, rm0, 1));
        rm0 = fmaxf(rm0, __shfl_xor_sync(0xffffffffu, rm0, 2));
        rm1 = fmaxf(rm1, __shfl_xor_sync(0xffffffffu, rm1, 1));
        rm1 = fmaxf(rm1, __shfl_xor_sync(0xffffffffu, rm1, 2));

        const float mn0 = fmaxf(m0, rm0);
        const float mn1 = fmaxf(m1, rm1);
        const float alpha0 = __expf(m0 - mn0);
        const float alpha1 = __expf(m1 - mn1);

        float rs0 = 0.0f, rs1 = 0.0f;
#pragma unroll
        for (int nf = 0; nf < 4; nf++) {
            const float p0v = __expf(sfr[nf][0] - mn0);
            const float p1v = __expf(sfr[nf][1] - mn0);
            const float p2v = __expf(sfr[nf][2] - mn1);
            const float p3v = __expf(sfr[nf][3] - mn1);
            rs0 += p0v + p1v;
            rs1 += p2v + p3v;
            float* pn = pw + nf * 160;
            {
                const int c = 2 * tig;
                const int tt = c & 3, hf = c >> 2;
                pn[tt * 40 + hf * 2 + 0] = f2tf_f(p0v);
                pn[tt * 40 + hf * 2 + 1] = f2tf_f(p2v);
            }
            {
                const int c = 2 * tig + 1;
                const int tt = c & 3, hf = c >> 2;
                pn[tt * 40 + hf * 2 + 0] = f2tf_f(p1v);
                pn[tt * 40 + hf * 2 + 1] = f2tf_f(p3v);
            }
        }
        rs0 += __shfl_xor_sync(0xffffffffu, rs0, 1);
        rs0 += __shfl_xor_sync(0xffffffffu, rs0, 2);
        rs1 += __shfl_xor_sync(0xffffffffu, rs1, 1);
        rs1 += __shfl_xor_sync(0xffffffffu, rs1, 2);

        l0 = l0 * alpha0 + rs0;  m0 = mn0;
        l1 = l1 * alpha1 + rs1;  m1 = mn1;
#pragma unroll
        for (int nf = 0; nf < 8; nf++) {
            o[nf][0] *= alpha0;  o[nf][1] *= alpha0;
            o[nf][2] *= alpha1;  o[nf][3] *= alpha1;
        }
        __syncwarp();

        // O += P V
#pragma unroll
        for (int ks2 = 0; ks2 < 4; ks2++) {
            const uint4 pa = *(const uint4*)(Psf + warp * 640 + ks2 * 160 + tig * 40 + gid * 4);
            const float* vk = Vsf + ks2 * 546 + tig * 136;
#pragma unroll
            for (int nf = 0; nf < 8; nf++) {
                const uint2 bf = *(const uint2*)(vk + (nf * 8 + gid) * 2);
                mma_tf32(o[nf], (const uint32_t*)&pa, bf.x, bf.y);
            }
        }

        if (more) STORE_TILE(s ^ 1)   // stage kt+1 into the other buffer
        __syncthreads();
    }
#undef LOAD_TILE
#undef STORE_TILE

    // epilogue: normalize, store to g_o[b][t][h*64+d]
    const float inv0 = 1.0f / l0;
    const float inv1 = 1.0f / l1;
    const int row0 = q0 + qr0;
    const int row1 = q0 + qr1;
#pragma unroll
    for (int nf = 0; nf < 8; nf++) {
        const int d = h * HDIM + nf * 8 + 2 * tig;
        *(float2*)(g_o + ((size_t)b * SEQ + row0) * KDIM + d) =
            make_float2(o[nf][0] * inv0, o[nf][1] * inv0);
        *(float2*)(g_o + ((size_t)b * SEQ + row1) * KDIM + d) =
            make_float2(o[nf][2] * inv1, o[nf][3] * inv1);
    }
}

// ---------------------------------------------------------------------------
extern "C" void kernel_launch(void* const* d_in, const int* in_sizes, int n_in,
                              void* d_out, int out_size)
{
    const float* x0      = (const float*)d_in[0];
    const int*   lengths = (const int*)d_in[1];   // int32 OR int64; decoded in-kernel
    const float* Wq      = (const float*)d_in[2];
    const float* Wk      = (const float*)d_in[3];
    const float* Wv      = (const float*)d_in[4];
    const float* Wu      = (const float*)d_in[5];
    const float* bu      = (const float*)d_in[6];
    float*       out     = (float*)d_out;

    // attention needs > 48 KB dynamic smem (host-side attribute, no alloc)
    cudaFuncSetAttribute(attn_tc, cudaFuncAttributeMaxDynamicSharedMemorySize, ATTN_SMEM);

    // QKV projections
    {
        dim3 grid(KDIM / 128, MROWS / 128, 3);
        gemm_tc<0><<<grid, 256, GEMM_SMEM>>>(x0, Wq, Wk, Wv, nullptr, nullptr);
    }
    // attention
    {
        dim3 grid(SEQ / 128, HEADS, BATCH);
        attn_tc<<<grid, 256, ATTN_SMEM>>>(lengths);
    }
    // output projection + bias
    {
        dim3 grid(KDIM / 128, MROWS / 128, 1);
        float* oScratch;
        cudaGetSymbolAddress((void**)&oScratch, g_o);
        gemm_tc<1><<<grid, 256, GEMM_SMEM>>>(oScratch, Wu, nullptr, nullptr, bu, out);
    }
}

// round 8
// speedup vs baseline: 4.1040x; 1.0169x over previous
#include <cuda_runtime.h>
#include <cuda_bf16.h>
#include <cstdint>

#define BATCH 4
#define SEQ   2048
#define KDIM  1024
#define HEADS 16
#define HDIM  64
#define MROWS (BATCH * SEQ)           // 8192
#define QK_SCALE 0.35355339059327373f // 64^(-1/4)

// Scratch (device globals — no allocations allowed)
__device__ float g_q[BATCH * HEADS * SEQ * HDIM];  // [b][h][t][d]
__device__ float g_k[BATCH * HEADS * SEQ * HDIM];
__device__ float g_v[BATCH * HEADS * SEQ * HDIM];
__device__ float g_o[BATCH * SEQ * KDIM];          // [b][t][h*64+d]

// ---------------------------------------------------------------------------
__device__ __forceinline__ uint32_t f2tf(float f) {
    uint32_t u;
    asm("cvt.rna.tf32.f32 %0, %1;" : "=r"(u) : "f"(f));
    return u;
}
__device__ __forceinline__ float f2tf_f(float f) { return __uint_as_float(f2tf(f)); }

__device__ __forceinline__ void mma_tf32(float c[4], const uint32_t a[4],
                                         uint32_t b0, uint32_t b1)
{
    asm volatile(
        "mma.sync.aligned.m16n8k8.row.col.f32.tf32.tf32.f32 "
        "{%0,%1,%2,%3}, {%4,%5,%6,%7}, {%8,%9}, {%0,%1,%2,%3};\n"
        : "+f"(c[0]), "+f"(c[1]), "+f"(c[2]), "+f"(c[3])
        : "r"(a[0]), "r"(a[1]), "r"(a[2]), "r"(a[3]), "r"(b0), "r"(b1));
}

// int64-vs-int32 robust length decode (lengths[b] >= 1 always)
__device__ __forceinline__ int decode_length(const int* l32, int b)
{
    const bool is64 = (l32[1] == 0) && (l32[3] == 0);
    return is64 ? l32[2 * b] : l32[b];
}

// ---------------------------------------------------------------------------
// tf32 GEMM: C[m,n] = sum_k A[m,k]*W[n,k].  CTA tile 256x128, BK=16,
// 8 warps as 4(m) x 2(n) => warp tile 64x64 (4 m-frags x 8 n-frags).
// Fragment-major smem, double-buffered, 1 sync per K-tile.
// Stage (floats, stride 6272):
//   A: [ks:2 (2080)][tig:4 (520)][p:128 x float4]   A-frag = 1 LDS.128
//   B at +4160: [ks:2 (1056)][tig:4 (264)][col:128 x float2]  B-frag = 1 LDS.64
// Dynamic smem = 2*6272*4 = 50176 B.
// ---------------------------------------------------------------------------
#define GEMM_SMEM 50176

template <int MODE>
__global__ void __launch_bounds__(256)
gemm_tc(const float* __restrict__ A,
        const float* __restrict__ W0,
        const float* __restrict__ W1,
        const float* __restrict__ W2,
        const float* __restrict__ bias,
        float* __restrict__ outPlain)
{
    extern __shared__ __align__(16) float sm[];

    const int tid  = threadIdx.x;
    const int warp = tid >> 5;
    const int lane = tid & 31;
    const int gid  = lane >> 2;
    const int tig  = lane & 3;
    const int warpM = (warp >> 1) * 64;   // 0,64,128,192
    const int warpN = (warp & 1) * 64;    // 0,64

    const float* W = W0;
    float* outQKV = nullptr;
    float scale = 1.0f;
    if (MODE == 0) {
        const int z = blockIdx.z;
        W      = (z == 0) ? W0 : (z == 1) ? W1 : W2;
        outQKV = (z == 0) ? g_q : (z == 1) ? g_k : g_v;
        scale  = (z == 2) ? 1.0f : QK_SCALE;
    }

    const int mBase = blockIdx.y * 256;
    const int nBase = blockIdx.x * 128;

    const int ldRow = tid >> 2;        // 0..63
    const int ldC   = (tid & 3) * 4;   // 0,4,8,12

    const float* Aptr = A + (size_t)(mBase + ldRow) * KDIM + ldC;
    const float* Bptr = W + (size_t)(nBase + ldRow) * KDIM + ldC;

    // staging constants (row -> p mapping; +64 rows => +32 in p)
    const int p0     = ((ldRow >> 4) << 3) | (ldRow & 7);   // 0..31
    const int rowbit = (ldRow >> 3) & 1;

    float4 ra[4];   // A rows ldRow + {0,64,128,192}
    float4 rb[2];   // B rows ldRow + {0,64}
#pragma unroll
    for (int i = 0; i < 4; i++) ra[i] = *(const float4*)(Aptr + (size_t)(64 * i) * KDIM);
#pragma unroll
    for (int i = 0; i < 2; i++) rb[i] = *(const float4*)(Bptr + (size_t)(64 * i) * KDIM);

#define STG_TILE(DST)                                                          \
    {                                                                          \
        float* Asf_ = (DST);                                                   \
        float* Bsf_ = (DST) + 4160;                                            \
        _Pragma("unroll")                                                      \
        for (int j_ = 0; j_ < 4; j_++) {                                       \
            const int c_  = ldC + j_;                                          \
            const int ks_ = c_ >> 3;                                           \
            const int w_  = c_ & 7;                                            \
            const int tg_ = w_ & 3;                                            \
            const int hf_ = w_ >> 2;                                           \
            float* ap_ = Asf_ + ks_ * 2080 + tg_ * 520;                        \
            float* bp_ = Bsf_ + ks_ * 1056 + tg_ * 264;                        \
            _Pragma("unroll")                                                  \
            for (int i_ = 0; i_ < 4; i_++) {                                   \
                const float av = (j_ == 0) ? ra[i_].x : (j_ == 1) ? ra[i_].y   \
                               : (j_ == 2) ? ra[i_].z : ra[i_].w;              \
                ap_[(p0 + 32 * i_) * 4 + hf_ * 2 + rowbit] = f2tf_f(av);       \
            }                                                                  \
            _Pragma("unroll")                                                  \
            for (int i_ = 0; i_ < 2; i_++) {                                   \
                const float bv = (j_ == 0) ? rb[i_].x : (j_ == 1) ? rb[i_].y   \
                               : (j_ == 2) ? rb[i_].z : rb[i_].w;              \
                bp_[(ldRow + 64 * i_) * 2 + hf_] = f2tf_f(bv);                 \
            }                                                                  \
        }                                                                      \
    }

    STG_TILE(sm)
    __syncthreads();

    float acc[4][8][4];
#pragma unroll
    for (int i = 0; i < 4; i++)
#pragma unroll
        for (int j = 0; j < 8; j++)
#pragma unroll
            for (int c = 0; c < 4; c++) acc[i][j][c] = 0.0f;

#pragma unroll 1
    for (int kt = 0; kt < KDIM / 16; ++kt) {
        const int s = kt & 1;
        const float* Asf = sm + s * 6272;
        const float* Bsf = Asf + 4160;

        const bool more = (kt < KDIM / 16 - 1);
        if (more) {
            Aptr += 16;  Bptr += 16;
#pragma unroll
            for (int i = 0; i < 4; i++) ra[i] = *(const float4*)(Aptr + (size_t)(64 * i) * KDIM);
#pragma unroll
            for (int i = 0; i < 2; i++) rb[i] = *(const float4*)(Bptr + (size_t)(64 * i) * KDIM);
        }

#pragma unroll
        for (int ks = 0; ks < 2; ++ks) {
            const float* ak = Asf + ks * 2080 + tig * 520;
            const float* bk = Bsf + ks * 1056 + tig * 264;
            uint4 af[4];
            uint2 bf[8];
#pragma unroll
            for (int mf = 0; mf < 4; mf++)
                af[mf] = *(const uint4*)(ak + ((warpM >> 1) + mf * 8 + gid) * 4);
#pragma unroll
            for (int nf = 0; nf < 8; nf++)
                bf[nf] = *(const uint2*)(bk + (warpN + nf * 8 + gid) * 2);
#pragma unroll
            for (int nf = 0; nf < 8; nf++)
#pragma unroll
                for (int mf = 0; mf < 4; mf++)
                    mma_tf32(acc[mf][nf], (const uint32_t*)&af[mf], bf[nf].x, bf[nf].y);
        }

        if (more) STG_TILE(sm + (s ^ 1) * 6272)
        __syncthreads();
    }
#undef STG_TILE

    // epilogue
#pragma unroll
    for (int mf = 0; mf < 4; mf++) {
        const int r0 = mBase + warpM + mf * 16 + gid;
        const int r1 = r0 + 8;
#pragma unroll
        for (int nf = 0; nf < 8; nf++) {
            const int col = nBase + warpN + nf * 8 + 2 * tig;
            if (MODE == 0) {
                const int h = col >> 6, d = col & 63;
                const int b0_ = r0 >> 11, t0_ = r0 & (SEQ - 1);
                const int b1_ = r1 >> 11, t1_ = r1 & (SEQ - 1);
                float* q0p = outQKV + (((size_t)(b0_ * HEADS + h) * SEQ + t0_) << 6) + d;
                float* q1p = outQKV + (((size_t)(b1_ * HEADS + h) * SEQ + t1_) << 6) + d;
                *(float2*)q0p = make_float2(acc[mf][nf][0] * scale, acc[mf][nf][1] * scale);
                *(float2*)q1p = make_float2(acc[mf][nf][2] * scale, acc[mf][nf][3] * scale);
            } else {
                const float2 bv = *(const float2*)(bias + col);
                *(float2*)(outPlain + (size_t)r0 * KDIM + col) =
                    make_float2(acc[mf][nf][0] + bv.x, acc[mf][nf][1] + bv.y);
                *(float2*)(outPlain + (size_t)r1 * KDIM + col) =
                    make_float2(acc[mf][nf][2] + bv.x, acc[mf][nf][3] + bv.y);
            }
        }
    }
}

// ---------------------------------------------------------------------------
// Flash attention, tf32 mma.sync. 256 queries per block, 8 warps; warp tile
// 32q x 32k (2 m-frags sharing all K/V B-frags). Fragment-major K/V/P smem,
// double-buffered K/V (1 block barrier per key tile), exact masked-tile skip.
// Smem (floats): K: s*2336 (x2) | V: 4672 + s*2184 (x2) | P: 9040 (10240)
// Total 19280 fl = 77120 B.
// ---------------------------------------------------------------------------
#define ATTN_SMEM 77120

__global__ void __launch_bounds__(256)
attn_tc(const int* __restrict__ lengths32)
{
    extern __shared__ __align__(16) float sm[];

    const int b  = blockIdx.z;
    const int h  = blockIdx.y;
    const int q0 = blockIdx.x * 256;
    const int tid  = threadIdx.x;
    const int warp = tid >> 5;
    const int lane = tid & 31;
    const int gid  = lane >> 2;
    const int tig  = lane & 3;

    float* const Psf = sm + 9040;

    const size_t headBase = (size_t)(b * HEADS + h) * SEQ * HDIM;
    const float* Qg = g_q + headBase + (size_t)q0 * HDIM;
    const float* Kg = g_k + headBase;
    const float* Vg = g_v + headBase;

    const int len = decode_length(lengths32, b);
    const int ktEnd = (len + 31) >> 5;

    // Q fragments: warp rows base qr = warp*32 + gid; m-frags at +0,+16
    const int qr = warp * 32 + gid;
    uint32_t aq[8][2][4];
#pragma unroll
    for (int ks = 0; ks < 8; ks++)
#pragma unroll
        for (int mf = 0; mf < 2; mf++) {
            const int r0 = qr + mf * 16;
            aq[ks][mf][0] = f2tf(Qg[(size_t)r0 * HDIM + ks * 8 + tig]);
            aq[ks][mf][1] = f2tf(Qg[(size_t)(r0 + 8) * HDIM + ks * 8 + tig]);
            aq[ks][mf][2] = f2tf(Qg[(size_t)r0 * HDIM + ks * 8 + tig + 4]);
            aq[ks][mf][3] = f2tf(Qg[(size_t)(r0 + 8) * HDIM + ks * 8 + tig + 4]);
        }

    float o[2][8][4];
#pragma unroll
    for (int mf = 0; mf < 2; mf++)
#pragma unroll
        for (int nf = 0; nf < 8; nf++)
#pragma unroll
            for (int c = 0; c < 4; c++) o[mf][nf][c] = 0.0f;
    float mrow[2][2], lrow[2][2];
#pragma unroll
    for (int mf = 0; mf < 2; mf++) {
        mrow[mf][0] = mrow[mf][1] = -1e30f;
        lrow[mf][0] = lrow[mf][1] = 0.0f;
    }

    float* const pwarp = Psf + warp * 1280;   // 2 m-frag slabs of 640 floats

    // staging constants
    const int v_ks2 = lane >> 3;
    const int v_tg  = lane & 3;
    const int v_hf  = (lane >> 2) & 1;

    float4 kv0, kv1, vv0, vv1;
#define LOAD_TILE(KB)                                                      \
    {                                                                      \
        const float* ksrc = Kg + (size_t)((KB) + lane) * HDIM + warp * 8;  \
        kv0 = *(const float4*)(ksrc);                                      \
        kv1 = *(const float4*)(ksrc + 4);                                  \
        const float* vsrc = Vg + (size_t)((KB) + lane) * HDIM + warp * 8;  \
        vv0 = *(const float4*)(vsrc);                                      \
        vv1 = *(const float4*)(vsrc + 4);                                  \
    }
#define STORE_TILE(S)                                                      \
    {                                                                      \
        float* Ksf_ = sm + (S) * 2336;                                     \
        float* Vsf_ = sm + 4672 + (S) * 2184;                              \
        float* kp = Ksf_ + warp * 292 + lane * 2;                          \
        kp[0 * 72 + 0] = f2tf_f(kv0.x);  kp[1 * 72 + 0] = f2tf_f(kv0.y);   \
        kp[2 * 72 + 0] = f2tf_f(kv0.z);  kp[3 * 72 + 0] = f2tf_f(kv0.w);   \
        kp[0 * 72 + 1] = f2tf_f(kv1.x);  kp[1 * 72 + 1] = f2tf_f(kv1.y);   \
        kp[2 * 72 + 1] = f2tf_f(kv1.z);  kp[3 * 72 + 1] = f2tf_f(kv1.w);   \
        float* vp = Vsf_ + v_ks2 * 546 + v_tg * 136 + v_hf;                \
        const int d0 = warp * 8;                                           \
        vp[(d0 + 0) * 2] = f2tf_f(vv0.x);  vp[(d0 + 1) * 2] = f2tf_f(vv0.y); \
        vp[(d0 + 2) * 2] = f2tf_f(vv0.z);  vp[(d0 + 3) * 2] = f2tf_f(vv0.w); \
        vp[(d0 + 4) * 2] = f2tf_f(vv1.x);  vp[(d0 + 5) * 2] = f2tf_f(vv1.y); \
        vp[(d0 + 6) * 2] = f2tf_f(vv1.z);  vp[(d0 + 7) * 2] = f2tf_f(vv1.w); \
    }

    LOAD_TILE(0)
    STORE_TILE(0)
    __syncthreads();

#pragma unroll 1
    for (int kt = 0; kt < ktEnd; ++kt) {
        const int s = kt & 1;
        const int kb = kt * 32;
        const bool more = (kt + 1 < ktEnd);

        if (more) LOAD_TILE(kb + 32)

        const float* Ksf = sm + s * 2336;
        const float* Vsf = sm + 4672 + s * 2184;

        // S = Q K^T
        float sfr[2][4][4];
#pragma unroll
        for (int mf = 0; mf < 2; mf++)
#pragma unroll
            for (int nf = 0; nf < 4; nf++)
#pragma unroll
                for (int c = 0; c < 4; c++) sfr[mf][nf][c] = 0.0f;
#pragma unroll
        for (int ks = 0; ks < 8; ks++) {
            const float* kk = Ksf + ks * 292 + tig * 72;
#pragma unroll
            for (int nf = 0; nf < 4; nf++) {
                const uint2 bf = *(const uint2*)(kk + (nf * 8 + gid) * 2);
                mma_tf32(sfr[0][nf], aq[ks][0], bf.x, bf.y);
                mma_tf32(sfr[1][nf], aq[ks][1], bf.x, bf.y);
            }
        }

        // key-padding penalty (boundary tile only)
        if (kb + 32 > len) {
#pragma unroll
            for (int nf = 0; nf < 4; nf++) {
                const int k0 = kb + nf * 8 + 2 * tig;
#pragma unroll
                for (int mf = 0; mf < 2; mf++) {
                    if (k0 >= len)     { sfr[mf][nf][0] += -10000.0f; sfr[mf][nf][2] += -10000.0f; }
                    if (k0 + 1 >= len) { sfr[mf][nf][1] += -10000.0f; sfr[mf][nf][3] += -10000.0f; }
                }
            }
        }

        // online softmax per m-frag
#pragma unroll
        for (int mf = 0; mf < 2; mf++) {
            float rm0 = -1e30f, rm1 = -1e30f;
#pragma unroll
            for (int nf = 0; nf < 4; nf++) {
                rm0 = fmaxf(rm0, fmaxf(sfr[mf][nf][0], sfr[mf][nf][1]));
                rm1 = fmaxf(rm1, fmaxf(sfr[mf][nf][2], sfr[mf][nf][3]));
            }
            rm0 = fmaxf(rm0, __shfl_xor_sync(0xffffffffu, rm0, 1));
            rm0 = fmaxf(rm0, __shfl_xor_sync(0xffffffffu, rm0, 2));
            rm1 = fmaxf(rm1, __shfl_xor_sync(0xffffffffu, rm1, 1));
            rm1 = fmaxf(rm1, __shfl_xor_sync(0xffffffffu, rm1, 2));

            const float mn0 = fmaxf(mrow[mf][0], rm0);
            const float mn1 = fmaxf(mrow[mf][1], rm1);
            const float alpha0 = __expf(mrow[mf][0] - mn0);
            const float alpha1 = __expf(mrow[mf][1] - mn1);

            float rs0 = 0.0f, rs1 = 0.0f;
            float* pmf = pwarp + mf * 640 + gid * 4;
#pragma unroll
            for (int nf = 0; nf < 4; nf++) {
                const float p0v = __expf(sfr[mf][nf][0] - mn0);
                const float p1v = __expf(sfr[mf][nf][1] - mn0);
                const float p2v = __expf(sfr[mf][nf][2] - mn1);
                const float p3v = __expf(sfr[mf][nf][3] - mn1);
                rs0 += p0v + p1v;
                rs1 += p2v + p3v;
                float* pn = pmf + nf * 160;
                {
                    const int c = 2 * tig;
                    const int tt = c & 3, hf = c >> 2;
                    pn[tt * 40 + hf * 2 + 0] = f2tf_f(p0v);
                    pn[tt * 40 + hf * 2 + 1] = f2tf_f(p2v);
                }
                {
                    const int c = 2 * tig + 1;
                    const int tt = c & 3, hf = c >> 2;
                    pn[tt * 40 + hf * 2 + 0] = f2tf_f(p1v);
                    pn[tt * 40 + hf * 2 + 1] = f2tf_f(p3v);
                }
            }
            rs0 += __shfl_xor_sync(0xffffffffu, rs0, 1);
            rs0 += __shfl_xor_sync(0xffffffffu, rs0, 2);
            rs1 += __shfl_xor_sync(0xffffffffu, rs1, 1);
            rs1 += __shfl_xor_sync(0xffffffffu, rs1, 2);

            lrow[mf][0] = lrow[mf][0] * alpha0 + rs0;  mrow[mf][0] = mn0;
            lrow[mf][1] = lrow[mf][1] * alpha1 + rs1;  mrow[mf][1] = mn1;
#pragma unroll
            for (int nf = 0; nf < 8; nf++) {
                o[mf][nf][0] *= alpha0;  o[mf][nf][1] *= alpha0;
                o[mf][nf][2] *= alpha1;  o[mf][nf][3] *= alpha1;
            }
        }
        __syncwarp();

        // O += P V  (V B-frags shared across the 2 m-frags)
#pragma unroll
        for (int ks2 = 0; ks2 < 4; ks2++) {
            uint4 pa[2];
            pa[0] = *(const uint4*)(pwarp + 0 * 640 + ks2 * 160 + tig * 40 + gid * 4);
            pa[1] = *(const uint4*)(pwarp + 1 * 640 + ks2 * 160 + tig * 40 + gid * 4);
            const float* vk = Vsf + ks2 * 546 + tig * 136;
#pragma unroll
            for (int nf = 0; nf < 8; nf++) {
                const uint2 bf = *(const uint2*)(vk + (nf * 8 + gid) * 2);
                mma_tf32(o[0][nf], (const uint32_t*)&pa[0], bf.x, bf.y);
                mma_tf32(o[1][nf], (const uint32_t*)&pa[1], bf.x, bf.y);
            }
        }

        if (more) STORE_TILE(s ^ 1)
        __syncthreads();
    }
#undef LOAD_TILE
#undef STORE_TILE

    // epilogue: normalize, store to g_o[b][t][h*64+d]
#pragma unroll
    for (int mf = 0; mf < 2; mf++) {
        const float inv0 = 1.0f / lrow[mf][0];
        const float inv1 = 1.0f / lrow[mf][1];
        const int row0 = q0 + qr + mf * 16;
        const int row1 = row0 + 8;
#pragma unroll
        for (int nf = 0; nf < 8; nf++) {
            const int d = h * HDIM + nf * 8 + 2 * tig;
            *(float2*)(g_o + ((size_t)b * SEQ + row0) * KDIM + d) =
                make_float2(o[mf][nf][0] * inv0, o[mf][nf][1] * inv0);
            *(float2*)(g_o + ((size_t)b * SEQ + row1) * KDIM + d) =
                make_float2(o[mf][nf][2] * inv1, o[mf][nf][3] * inv1);
        }
    }
}

// ---------------------------------------------------------------------------
extern "C" void kernel_launch(void* const* d_in, const int* in_sizes, int n_in,
                              void* d_out, int out_size)
{
    const float* x0      = (const float*)d_in[0];
    const int*   lengths = (const int*)d_in[1];   // int32 OR int64; decoded in-kernel
    const float* Wq      = (const float*)d_in[2];
    const float* Wk      = (const float*)d_in[3];
    const float* Wv      = (const float*)d_in[4];
    const float* Wu      = (const float*)d_in[5];
    const float* bu      = (const float*)d_in[6];
    float*       out     = (float*)d_out;

    // >48KB dynamic smem opt-in (host-side attribute, no allocation)
    cudaFuncSetAttribute(gemm_tc<0>, cudaFuncAttributeMaxDynamicSharedMemorySize, GEMM_SMEM);
    cudaFuncSetAttribute(gemm_tc<1>, cudaFuncAttributeMaxDynamicSharedMemorySize, GEMM_SMEM);
    cudaFuncSetAttribute(attn_tc,    cudaFuncAttributeMaxDynamicSharedMemorySize, ATTN_SMEM);

    // QKV projections
    {
        dim3 grid(KDIM / 128, MROWS / 256, 3);
        gemm_tc<0><<<grid, 256, GEMM_SMEM>>>(x0, Wq, Wk, Wv, nullptr, nullptr);
    }
    // attention
    {
        dim3 grid(SEQ / 256, HEADS, BATCH);
        attn_tc<<<grid, 256, ATTN_SMEM>>>(lengths);
    }
    // output projection + bias
    {
        dim3 grid(KDIM / 128, MROWS / 256, 1);
        float* oScratch;
        cudaGetSymbolAddress((void**)&oScratch, g_o);
        gemm_tc<1><<<grid, 256, GEMM_SMEM>>>(oScratch, Wu, nullptr, nullptr, bu, out);
    }
}

// round 9
// speedup vs baseline: 4.4262x; 1.0785x over previous
#include <cuda_runtime.h>
#include <cuda_bf16.h>
#include <cstdint>

#define BATCH 4
#define SEQ   2048
#define KDIM  1024
#define HEADS 16
#define HDIM  64
#define MROWS (BATCH * SEQ)           // 8192
#define QK_SCALE 0.35355339059327373f // 64^(-1/4)

// Scratch (device globals — no allocations allowed)
__device__ float g_q[BATCH * HEADS * SEQ * HDIM];  // [b][h][t][d]
__device__ float g_k[BATCH * HEADS * SEQ * HDIM];
__device__ float g_v[BATCH * HEADS * SEQ * HDIM];
__device__ float g_o[BATCH * SEQ * KDIM];          // [b][t][h*64+d]

// ---------------------------------------------------------------------------
__device__ __forceinline__ uint32_t f2tf(float f) {
    uint32_t u;
    asm("cvt.rna.tf32.f32 %0, %1;" : "=r"(u) : "f"(f));
    return u;
}
__device__ __forceinline__ float f2tf_f(float f) { return __uint_as_float(f2tf(f)); }

__device__ __forceinline__ void mma_tf32(float c[4], const uint32_t a[4],
                                         uint32_t b0, uint32_t b1)
{
    asm volatile(
        "mma.sync.aligned.m16n8k8.row.col.f32.tf32.tf32.f32 "
        "{%0,%1,%2,%3}, {%4,%5,%6,%7}, {%8,%9}, {%0,%1,%2,%3};\n"
        : "+f"(c[0]), "+f"(c[1]), "+f"(c[2]), "+f"(c[3])
        : "r"(a[0]), "r"(a[1]), "r"(a[2]), "r"(a[3]), "r"(b0), "r"(b1));
}

// int64-vs-int32 robust length decode (lengths[b] >= 1 always)
__device__ __forceinline__ int decode_length(const int* l32, int b)
{
    const bool is64 = (l32[1] == 0) && (l32[3] == 0);
    return is64 ? l32[2 * b] : l32[b];
}

// ---------------------------------------------------------------------------
// tf32 GEMM (ROUND-6 CONFIG — measured best): CTA 128x128, BK=16, 8 warps as
// 2(m) x 4(n), warp tile 64x32. Fragment-major smem, double-buffered,
// 1 sync/K-tile. 124 regs -> 2 CTAs/SM.
// Stage (floats, stride 4224): A: [ks:2 (1056)][tig:4 (264)][p:64 x float4]
//                              B at +2112: [ks:2][tig:4 (264)][col:128 x float2]
// ---------------------------------------------------------------------------
#define GEMM_SMEM 33792

template <int MODE>
__global__ void __launch_bounds__(256)
gemm_tc(const float* __restrict__ A,
        const float* __restrict__ W0,
        const float* __restrict__ W1,
        const float* __restrict__ W2,
        const float* __restrict__ bias,
        float* __restrict__ outPlain)
{
    extern __shared__ __align__(16) float sm[];

    const int tid  = threadIdx.x;
    const int warp = tid >> 5;
    const int lane = tid & 31;
    const int gid  = lane >> 2;
    const int tig  = lane & 3;
    const int warpM = (warp & 1) * 64;
    const int warpN = (warp >> 1) * 32;

    const float* W = W0;
    float* outQKV = nullptr;
    float scale = 1.0f;
    if (MODE == 0) {
        const int z = blockIdx.z;
        W      = (z == 0) ? W0 : (z == 1) ? W1 : W2;
        outQKV = (z == 0) ? g_q : (z == 1) ? g_k : g_v;
        scale  = (z == 2) ? 1.0f : QK_SCALE;
    }

    const int mBase = blockIdx.y * 128;
    const int nBase = blockIdx.x * 128;

    const int ldRow = tid >> 2;        // 0..63
    const int ldC   = (tid & 3) * 4;   // 0,4,8,12

    const float* Aptr = A + (size_t)(mBase + ldRow) * KDIM + ldC;
    const float* Bptr = W + (size_t)(nBase + ldRow) * KDIM + ldC;

    const int p0     = ((ldRow >> 4) << 3) | (ldRow & 7);
    const int rowbit = (ldRow >> 3) & 1;

    float4 ra0 = *(const float4*)(Aptr);
    float4 ra1 = *(const float4*)(Aptr + (size_t)64 * KDIM);
    float4 rb0 = *(const float4*)(Bptr);
    float4 rb1 = *(const float4*)(Bptr + (size_t)64 * KDIM);

#define STG_TILE(DST)                                                 \
    {                                                                 \
        float* Asf_ = (DST);                                          \
        float* Bsf_ = (DST) + 2112;                                   \
        _Pragma("unroll")                                             \
        for (int j_ = 0; j_ < 4; j_++) {                              \
            const int c_  = ldC + j_;                                 \
            const int ks_ = c_ >> 3;                                  \
            const int w_  = c_ & 7;                                   \
            const int tg_ = w_ & 3;                                   \
            const int hf_ = w_ >> 2;                                  \
            float* ap_ = Asf_ + ks_ * 1056 + tg_ * 264;               \
            float* bp_ = Bsf_ + ks_ * 1056 + tg_ * 264;               \
            const float ax0 = (j_ == 0) ? ra0.x : (j_ == 1) ? ra0.y : (j_ == 2) ? ra0.z : ra0.w; \
            const float ax1 = (j_ == 0) ? ra1.x : (j_ == 1) ? ra1.y : (j_ == 2) ? ra1.z : ra1.w; \
            const float bx0 = (j_ == 0) ? rb0.x : (j_ == 1) ? rb0.y : (j_ == 2) ? rb0.z : rb0.w; \
            const float bx1 = (j_ == 0) ? rb1.x : (j_ == 1) ? rb1.y : (j_ == 2) ? rb1.z : rb1.w; \
            ap_[p0 * 4 + hf_ * 2 + rowbit]        = f2tf_f(ax0);      \
            ap_[(p0 + 32) * 4 + hf_ * 2 + rowbit] = f2tf_f(ax1);      \
            bp_[ldRow * 2 + hf_]                  = f2tf_f(bx0);      \
            bp_[(ldRow + 64) * 2 + hf_]           = f2tf_f(bx1);      \
        }                                                             \
    }

    STG_TILE(sm)
    __syncthreads();

    float acc[4][4][4];
#pragma unroll
    for (int i = 0; i < 4; i++)
#pragma unroll
        for (int j = 0; j < 4; j++)
#pragma unroll
            for (int c = 0; c < 4; c++) acc[i][j][c] = 0.0f;

#pragma unroll 1
    for (int kt = 0; kt < KDIM / 16; ++kt) {
        const int s = kt & 1;
        const float* Asf = sm + s * 4224;
        const float* Bsf = Asf + 2112;

        const bool more = (kt < KDIM / 16 - 1);
        if (more) {
            Aptr += 16; Bptr += 16;
            ra0 = *(const float4*)(Aptr);
            ra1 = *(const float4*)(Aptr + (size_t)64 * KDIM);
            rb0 = *(const float4*)(Bptr);
            rb1 = *(const float4*)(Bptr + (size_t)64 * KDIM);
        }

#pragma unroll
        for (int ks = 0; ks < 2; ++ks) {
            const float* ak = Asf + ks * 1056 + tig * 264;
            const float* bk = Bsf + ks * 1056 + tig * 264;
            uint4 af[4];
            uint2 bf[4];
#pragma unroll
            for (int mf = 0; mf < 4; mf++)
                af[mf] = *(const uint4*)(ak + ((warpM >> 1) + mf * 8 + gid) * 4);
#pragma unroll
            for (int nf = 0; nf < 4; nf++)
                bf[nf] = *(const uint2*)(bk + (warpN + nf * 8 + gid) * 2);
#pragma unroll
            for (int nf = 0; nf < 4; nf++)
#pragma unroll
                for (int mf = 0; mf < 4; mf++)
                    mma_tf32(acc[mf][nf], (const uint32_t*)&af[mf], bf[nf].x, bf[nf].y);
        }

        if (more) STG_TILE(sm + (s ^ 1) * 4224)
        __syncthreads();
    }
#undef STG_TILE

#pragma unroll
    for (int mf = 0; mf < 4; mf++) {
        const int r0 = mBase + warpM + mf * 16 + gid;
        const int r1 = r0 + 8;
#pragma unroll
        for (int nf = 0; nf < 4; nf++) {
            const int col = nBase + warpN + nf * 8 + 2 * tig;
            if (MODE == 0) {
                const int h = col >> 6, d = col & 63;
                const int b0_ = r0 >> 11, t0_ = r0 & (SEQ - 1);
                const int b1_ = r1 >> 11, t1_ = r1 & (SEQ - 1);
                float* q0p = outQKV + (((size_t)(b0_ * HEADS + h) * SEQ + t0_) << 6) + d;
                float* q1p = outQKV + (((size_t)(b1_ * HEADS + h) * SEQ + t1_) << 6) + d;
                *(float2*)q0p = make_float2(acc[mf][nf][0] * scale, acc[mf][nf][1] * scale);
                *(float2*)q1p = make_float2(acc[mf][nf][2] * scale, acc[mf][nf][3] * scale);
            } else {
                const float2 bv = *(const float2*)(bias + col);
                *(float2*)(outPlain + (size_t)r0 * KDIM + col) =
                    make_float2(acc[mf][nf][0] + bv.x, acc[mf][nf][1] + bv.y);
                *(float2*)(outPlain + (size_t)r1 * KDIM + col) =
                    make_float2(acc[mf][nf][2] + bv.x, acc[mf][nf][3] + bv.y);
            }
        }
    }
}

// ---------------------------------------------------------------------------
// Flash attention (ROUND-8 CONFIG — measured best): 256 queries per block,
// 8 warps; warp tile 32q x 32k (2 m-frags share K/V B-frags). Fragment-major
// K/V/P smem, double-buffered K/V, 1 block barrier per key tile, exact
// masked-tile skip.
// Smem (floats): K: s*2336 (x2) | V: 4672 + s*2184 (x2) | P: 9040 (10240)
// Total 19280 fl = 77120 B.
// ---------------------------------------------------------------------------
#define ATTN_SMEM 77120

__global__ void __launch_bounds__(256)
attn_tc(const int* __restrict__ lengths32)
{
    extern __shared__ __align__(16) float sm[];

    const int b  = blockIdx.z;
    const int h  = blockIdx.y;
    const int q0 = blockIdx.x * 256;
    const int tid  = threadIdx.x;
    const int warp = tid >> 5;
    const int lane = tid & 31;
    const int gid  = lane >> 2;
    const int tig  = lane & 3;

    float* const Psf = sm + 9040;

    const size_t headBase = (size_t)(b * HEADS + h) * SEQ * HDIM;
    const float* Qg = g_q + headBase + (size_t)q0 * HDIM;
    const float* Kg = g_k + headBase;
    const float* Vg = g_v + headBase;

    const int len = decode_length(lengths32, b);
    const int ktEnd = (len + 31) >> 5;

    const int qr = warp * 32 + gid;
    uint32_t aq[8][2][4];
#pragma unroll
    for (int ks = 0; ks < 8; ks++)
#pragma unroll
        for (int mf = 0; mf < 2; mf++) {
            const int r0 = qr + mf * 16;
            aq[ks][mf][0] = f2tf(Qg[(size_t)r0 * HDIM + ks * 8 + tig]);
            aq[ks][mf][1] = f2tf(Qg[(size_t)(r0 + 8) * HDIM + ks * 8 + tig]);
            aq[ks][mf][2] = f2tf(Qg[(size_t)r0 * HDIM + ks * 8 + tig + 4]);
            aq[ks][mf][3] = f2tf(Qg[(size_t)(r0 + 8) * HDIM + ks * 8 + tig + 4]);
        }

    float o[2][8][4];
#pragma unroll
    for (int mf = 0; mf < 2; mf++)
#pragma unroll
        for (int nf = 0; nf < 8; nf++)
#pragma unroll
            for (int c = 0; c < 4; c++) o[mf][nf][c] = 0.0f;
    float mrow[2][2], lrow[2][2];
#pragma unroll
    for (int mf = 0; mf < 2; mf++) {
        mrow[mf][0] = mrow[mf][1] = -1e30f;
        lrow[mf][0] = lrow[mf][1] = 0.0f;
    }

    float* const pwarp = Psf + warp * 1280;

    const int v_ks2 = lane >> 3;
    const int v_tg  = lane & 3;
    const int v_hf  = (lane >> 2) & 1;

    float4 kv0, kv1, vv0, vv1;
#define LOAD_TILE(KB)                                                      \
    {                                                                      \
        const float* ksrc = Kg + (size_t)((KB) + lane) * HDIM + warp * 8;  \
        kv0 = *(const float4*)(ksrc);                                      \
        kv1 = *(const float4*)(ksrc + 4);                                  \
        const float* vsrc = Vg + (size_t)((KB) + lane) * HDIM + warp * 8;  \
        vv0 = *(const float4*)(vsrc);                                      \
        vv1 = *(const float4*)(vsrc + 4);                                  \
    }
#define STORE_TILE(S)                                                      \
    {                                                                      \
        float* Ksf_ = sm + (S) * 2336;                                     \
        float* Vsf_ = sm + 4672 + (S) * 2184;                              \
        float* kp = Ksf_ + warp * 292 + lane * 2;                          \
        kp[0 * 72 + 0] = f2tf_f(kv0.x);  kp[1 * 72 + 0] = f2tf_f(kv0.y);   \
        kp[2 * 72 + 0] = f2tf_f(kv0.z);  kp[3 * 72 + 0] = f2tf_f(kv0.w);   \
        kp[0 * 72 + 1] = f2tf_f(kv1.x);  kp[1 * 72 + 1] = f2tf_f(kv1.y);   \
        kp[2 * 72 + 1] = f2tf_f(kv1.z);  kp[3 * 72 + 1] = f2tf_f(kv1.w);   \
        float* vp = Vsf_ + v_ks2 * 546 + v_tg * 136 + v_hf;                \
        const int d0 = warp * 8;                                           \
        vp[(d0 + 0) * 2] = f2tf_f(vv0.x);  vp[(d0 + 1) * 2] = f2tf_f(vv0.y); \
        vp[(d0 + 2) * 2] = f2tf_f(vv0.z);  vp[(d0 + 3) * 2] = f2tf_f(vv0.w); \
        vp[(d0 + 4) * 2] = f2tf_f(vv1.x);  vp[(d0 + 5) * 2] = f2tf_f(vv1.y); \
        vp[(d0 + 6) * 2] = f2tf_f(vv1.z);  vp[(d0 + 7) * 2] = f2tf_f(vv1.w); \
    }

    LOAD_TILE(0)
    STORE_TILE(0)
    __syncthreads();

#pragma unroll 1
    for (int kt = 0; kt < ktEnd; ++kt) {
        const int s = kt & 1;
        const int kb = kt * 32;
        const bool more = (kt + 1 < ktEnd);

        if (more) LOAD_TILE(kb + 32)

        const float* Ksf = sm + s * 2336;
        const float* Vsf = sm + 4672 + s * 2184;

        float sfr[2][4][4];
#pragma unroll
        for (int mf = 0; mf < 2; mf++)
#pragma unroll
            for (int nf = 0; nf < 4; nf++)
#pragma unroll
                for (int c = 0; c < 4; c++) sfr[mf][nf][c] = 0.0f;
#pragma unroll
        for (int ks = 0; ks < 8; ks++) {
            const float* kk = Ksf + ks * 292 + tig * 72;
#pragma unroll
            for (int nf = 0; nf < 4; nf++) {
                const uint2 bf = *(const uint2*)(kk + (nf * 8 + gid) * 2);
                mma_tf32(sfr[0][nf], aq[ks][0], bf.x, bf.y);
                mma_tf32(sfr[1][nf], aq[ks][1], bf.x, bf.y);
            }
        }

        if (kb + 32 > len) {
#pragma unroll
            for (int nf = 0; nf < 4; nf++) {
                const int k0 = kb + nf * 8 + 2 * tig;
#pragma unroll
                for (int mf = 0; mf < 2; mf++) {
                    if (k0 >= len)     { sfr[mf][nf][0] += -10000.0f; sfr[mf][nf][2] += -10000.0f; }
                    if (k0 + 1 >= len) { sfr[mf][nf][1] += -10000.0f; sfr[mf][nf][3] += -10000.0f; }
                }
            }
        }

#pragma unroll
        for (int mf = 0; mf < 2; mf++) {
            float rm0 = -1e30f, rm1 = -1e30f;
#pragma unroll
            for (int nf = 0; nf < 4; nf++) {
                rm0 = fmaxf(rm0, fmaxf(sfr[mf][nf][0], sfr[mf][nf][1]));
                rm1 = fmaxf(rm1, fmaxf(sfr[mf][nf][2], sfr[mf][nf][3]));
            }
            rm0 = fmaxf(rm0, __shfl_xor_sync(0xffffffffu, rm0, 1));
            rm0 = fmaxf(rm0, __shfl_xor_sync(0xffffffffu, rm0, 2));
            rm1 = fmaxf(rm1, __shfl_xor_sync(0xffffffffu, rm1, 1));
            rm1 = fmaxf(rm1, __shfl_xor_sync(0xffffffffu, rm1, 2));

            const float mn0 = fmaxf(mrow[mf][0], rm0);
            const float mn1 = fmaxf(mrow[mf][1], rm1);
            const float alpha0 = __expf(mrow[mf][0] - mn0);
            const float alpha1 = __expf(mrow[mf][1] - mn1);

            float rs0 = 0.0f, rs1 = 0.0f;
            float* pmf = pwarp + mf * 640 + gid * 4;
#pragma unroll
            for (int nf = 0; nf < 4; nf++) {
                const float p0v = __expf(sfr[mf][nf][0] - mn0);
                const float p1v = __expf(sfr[mf][nf][1] - mn0);
                const float p2v = __expf(sfr[mf][nf][2] - mn1);
                const float p3v = __expf(sfr[mf][nf][3] - mn1);
                rs0 += p0v + p1v;
                rs1 += p2v + p3v;
                float* pn = pmf + nf * 160;
                {
                    const int c = 2 * tig;
                    const int tt = c & 3, hf = c >> 2;
                    pn[tt * 40 + hf * 2 + 0] = f2tf_f(p0v);
                    pn[tt * 40 + hf * 2 + 1] = f2tf_f(p2v);
                }
                {
                    const int c = 2 * tig + 1;
                    const int tt = c & 3, hf = c >> 2;
                    pn[tt * 40 + hf * 2 + 0] = f2tf_f(p1v);
                    pn[tt * 40 + hf * 2 + 1] = f2tf_f(p3v);
                }
            }
            rs0 += __shfl_xor_sync(0xffffffffu, rs0, 1);
            rs0 += __shfl_xor_sync(0xffffffffu, rs0, 2);
            rs1 += __shfl_xor_sync(0xffffffffu, rs1, 1);
            rs1 += __shfl_xor_sync(0xffffffffu, rs1, 2);

            lrow[mf][0] = lrow[mf][0] * alpha0 + rs0;  mrow[mf][0] = mn0;
            lrow[mf][1] = lrow[mf][1] * alpha1 + rs1;  mrow[mf][1] = mn1;
#pragma unroll
            for (int nf = 0; nf < 8; nf++) {
                o[mf][nf][0] *= alpha0;  o[mf][nf][1] *= alpha0;
                o[mf][nf][2] *= alpha1;  o[mf][nf][3] *= alpha1;
            }
        }
        __syncwarp();

#pragma unroll
        for (int ks2 = 0; ks2 < 4; ks2++) {
            uint4 pa[2];
            pa[0] = *(const uint4*)(pwarp + 0 * 640 + ks2 * 160 + tig * 40 + gid * 4);
            pa[1] = *(const uint4*)(pwarp + 1 * 640 + ks2 * 160 + tig * 40 + gid * 4);
            const float* vk = Vsf + ks2 * 546 + tig * 136;
#pragma unroll
            for (int nf = 0; nf < 8; nf++) {
                const uint2 bf = *(const uint2*)(vk + (nf * 8 + gid) * 2);
                mma_tf32(o[0][nf], (const uint32_t*)&pa[0], bf.x, bf.y);
                mma_tf32(o[1][nf], (const uint32_t*)&pa[1], bf.x, bf.y);
            }
        }

        if (more) STORE_TILE(s ^ 1)
        __syncthreads();
    }
#undef LOAD_TILE
#undef STORE_TILE

#pragma unroll
    for (int mf = 0; mf < 2; mf++) {
        const float inv0 = 1.0f / lrow[mf][0];
        const float inv1 = 1.0f / lrow[mf][1];
        const int row0 = q0 + qr + mf * 16;
        const int row1 = row0 + 8;
#pragma unroll
        for (int nf = 0; nf < 8; nf++) {
            const int d = h * HDIM + nf * 8 + 2 * tig;
            *(float2*)(g_o + ((size_t)b * SEQ + row0) * KDIM + d) =
                make_float2(o[mf][nf][0] * inv0, o[mf][nf][1] * inv0);
            *(float2*)(g_o + ((size_t)b * SEQ + row1) * KDIM + d) =
                make_float2(o[mf][nf][2] * inv1, o[mf][nf][3] * inv1);
        }
    }
}

// ---------------------------------------------------------------------------
extern "C" void kernel_launch(void* const* d_in, const int* in_sizes, int n_in,
                              void* d_out, int out_size)
{
    const float* x0      = (const float*)d_in[0];
    const int*   lengths = (const int*)d_in[1];   // int32 OR int64; decoded in-kernel
    const float* Wq      = (const float*)d_in[2];
    const float* Wk      = (const float*)d_in[3];
    const float* Wv      = (const float*)d_in[4];
    const float* Wu      = (const float*)d_in[5];
    const float* bu      = (const float*)d_in[6];
    float*       out     = (float*)d_out;

    cudaFuncSetAttribute(attn_tc, cudaFuncAttributeMaxDynamicSharedMemorySize, ATTN_SMEM);

    // QKV projections (round-6 GEMM config)
    {
        dim3 grid(KDIM / 128, MROWS / 128, 3);
        gemm_tc<0><<<grid, 256, GEMM_SMEM>>>(x0, Wq, Wk, Wv, nullptr, nullptr);
    }
    // attention (round-8 config)
    {
        dim3 grid(SEQ / 256, HEADS, BATCH);
        attn_tc<<<grid, 256, ATTN_SMEM>>>(lengths);
    }
    // output projection + bias
    {
        dim3 grid(KDIM / 128, MROWS / 128, 1);
        float* oScratch;
        cudaGetSymbolAddress((void**)&oScratch, g_o);
        gemm_tc<1><<<grid, 256, GEMM_SMEM>>>(oScratch, Wu, nullptr, nullptr, bu, out);
    }
}